// round 9
// baseline (speedup 1.0000x reference)
#include <cuda_runtime.h>
#include <cuda_bf16.h>
#include <cstdint>

#define NNODES 100000
#define NEDGES 1600000
#define DIM 256
#define DIM2 512
#define BN_EPS 1e-5f

// ---------------- scratch (static device globals; no dynamic alloc) -----------
__device__ int    g_is64;
__device__ int    g_deg[NNODES];
__device__ int    g_rowptr[NNODES + 1];
__device__ int    g_cursor[NNODES];
__device__ int    g_edgesrc[NEDGES];
__device__ float  g_bufA[(size_t)NNODES * DIM];    // h0 (tf32-rounded), later h2
__device__ float  g_bufB[(size_t)NNODES * DIM2];   // h1 (tf32-rounded)
__device__ float  g_WT1[(size_t)DIM2 * DIM];       // W1^T, tf32-rounded
__device__ float  g_WT2[(size_t)DIM * DIM2];       // W2^T, tf32-rounded
__device__ float  g_bnsum[DIM];
__device__ float  g_bnsumsq[DIM];

#define SCAN_CHUNK 1024
#define SCAN_NB ((NNODES + SCAN_CHUNK - 1) / SCAN_CHUNK)   // 98
__device__ int g_bsum[SCAN_NB];
__device__ int g_boff[SCAN_NB];

// ---------------- helpers ------------------------------------------------------
__device__ __forceinline__ uint32_t smem_u32(const void* p) {
    uint32_t a;
    asm("{ .reg .u64 t; cvta.to.shared.u64 t, %1; cvt.u32.u64 %0, t; }"
        : "=r"(a) : "l"(p));
    return a;
}
__device__ __forceinline__ float f2tf32f(float f) {
    uint32_t r;
    asm("cvt.rna.tf32.f32 %0, %1;" : "=r"(r) : "f"(f));
    return __uint_as_float(r);
}
#define CP_ASYNC16Z(dst, src, sz) \
    asm volatile("cp.async.cg.shared.global [%0], [%1], 16, %2;" \
                 :: "r"(dst), "l"(src), "r"(sz) : "memory")
#define CP_ASYNC16(dst, src) \
    asm volatile("cp.async.cg.shared.global [%0], [%1], 16;" \
                 :: "r"(dst), "l"(src) : "memory")
#define CP_COMMIT() asm volatile("cp.async.commit_group;" ::: "memory")
#define CP_WAIT(n)  asm volatile("cp.async.wait_group %0;" :: "n"(n) : "memory")

__device__ __forceinline__ int load_idx(const void* p, int e, int is64) {
    return is64 ? (int)((const long long*)p)[e] : ((const int*)p)[e];
}

// ---------------- zero + index-dtype detect ------------------------------------
__global__ void k_zero(const int* __restrict__ dst_raw) {
    int i = blockIdx.x * blockDim.x + threadIdx.x;
    if (i < NNODES) g_deg[i] = 0;
    if (i < DIM) { g_bnsum[i] = 0.f; g_bnsumsq[i] = 0.f; }
    if (i == 0) {
        int is64 = 1;
        for (int k = 0; k < 64; k++)
            if (dst_raw[2 * k + 1] != 0) { is64 = 0; break; }
        g_is64 = is64;
    }
}

// ---------------- CSR build ----------------------------------------------------
__global__ void k_hist(const void* __restrict__ dst) {
    int e0 = (blockIdx.x * blockDim.x + threadIdx.x) * 2;
    int is64 = g_is64;
    if (e0 + 1 < NEDGES) {
        int d0, d1;
        if (is64) {
            longlong2 v = __ldg(&((const longlong2*)dst)[e0 >> 1]);
            d0 = (int)v.x; d1 = (int)v.y;
        } else {
            int2 v = __ldg(&((const int2*)dst)[e0 >> 1]);
            d0 = v.x; d1 = v.y;
        }
        atomicAdd(&g_deg[d0], 1);
        atomicAdd(&g_deg[d1], 1);
    } else if (e0 < NEDGES) {
        atomicAdd(&g_deg[load_idx(dst, e0, is64)], 1);
    }
}
__global__ void k_scan1() {
    __shared__ int sm[SCAN_CHUNK];
    int b = blockIdx.x, tid = threadIdx.x;
    int idx = b * SCAN_CHUNK + tid;
    int v = (idx < NNODES) ? g_deg[idx] : 0;
    sm[tid] = v;
    __syncthreads();
    for (int s = 1; s < SCAN_CHUNK; s <<= 1) {
        int t = (tid >= s) ? sm[tid - s] : 0;
        __syncthreads();
        sm[tid] += t;
        __syncthreads();
    }
    if (idx < NNODES) g_rowptr[idx] = sm[tid] - v;
    if (tid == SCAN_CHUNK - 1) g_bsum[b] = sm[tid];
}
__global__ void k_scan2() {
    __shared__ int sm[128];
    int tid = threadIdx.x;
    int v = (tid < SCAN_NB) ? g_bsum[tid] : 0;
    sm[tid] = v;
    __syncthreads();
    for (int s = 1; s < 128; s <<= 1) {
        int t = (tid >= s) ? sm[tid - s] : 0;
        __syncthreads();
        sm[tid] += t;
        __syncthreads();
    }
    if (tid < SCAN_NB) g_boff[tid] = sm[tid] - v;
    if (tid == 127) g_rowptr[NNODES] = sm[127];
}
__global__ void k_scan3() {
    int i = blockIdx.x * blockDim.x + threadIdx.x;
    if (i < NNODES) {
        int r = g_rowptr[i] + g_boff[i >> 10];
        g_rowptr[i] = r;
        g_cursor[i] = r;
    }
}
__global__ void k_scatter(const void* __restrict__ src,
                          const void* __restrict__ dst) {
    int e0 = (blockIdx.x * blockDim.x + threadIdx.x) * 2;
    int is64 = g_is64;
    if (e0 + 1 < NEDGES) {
        int s0, s1, d0, d1;
        if (is64) {
            longlong2 vs = __ldg(&((const longlong2*)src)[e0 >> 1]);
            longlong2 vd = __ldg(&((const longlong2*)dst)[e0 >> 1]);
            s0 = (int)vs.x; s1 = (int)vs.y;
            d0 = (int)vd.x; d1 = (int)vd.y;
        } else {
            int2 vs = __ldg(&((const int2*)src)[e0 >> 1]);
            int2 vd = __ldg(&((const int2*)dst)[e0 >> 1]);
            s0 = vs.x; s1 = vs.y;
            d0 = vd.x; d1 = vd.y;
        }
        int p0 = atomicAdd(&g_cursor[d0], 1);
        g_edgesrc[p0] = s0;
        int p1 = atomicAdd(&g_cursor[d1], 1);
        g_edgesrc[p1] = s1;
    } else if (e0 < NEDGES) {
        int d = load_idx(dst, e0, is64);
        int pos = atomicAdd(&g_cursor[d], 1);
        g_edgesrc[pos] = load_idx(src, e0, is64);
    }
}

// ---------------- aggregation: h0 = tf32((1+eps)*x + sum x[src]) ---------------
__global__ __launch_bounds__(256) void k_aggregate(
    const float* __restrict__ x, const float* __restrict__ eps) {
    int grp = threadIdx.x >> 6;              // 0..3
    int t = threadIdx.x & 63;                // float4 column
    int n = blockIdx.x * 4 + grp;
    if (n >= NNODES) return;
    const float4* x4 = (const float4*)x;

    int beg = g_rowptr[n];
    int end = g_rowptr[n + 1];
    float4 a0 = make_float4(0.f, 0.f, 0.f, 0.f);
    float4 a1 = make_float4(0.f, 0.f, 0.f, 0.f);
    float4 a2 = make_float4(0.f, 0.f, 0.f, 0.f);
    float4 a3 = make_float4(0.f, 0.f, 0.f, 0.f);
    int j = beg;
    for (; j + 4 <= end; j += 4) {
        int s0 = g_edgesrc[j];
        int s1 = g_edgesrc[j + 1];
        int s2 = g_edgesrc[j + 2];
        int s3 = g_edgesrc[j + 3];
        float4 v0 = __ldg(&x4[(size_t)s0 * 64 + t]);
        float4 v1 = __ldg(&x4[(size_t)s1 * 64 + t]);
        float4 v2 = __ldg(&x4[(size_t)s2 * 64 + t]);
        float4 v3 = __ldg(&x4[(size_t)s3 * 64 + t]);
        a0.x += v0.x; a0.y += v0.y; a0.z += v0.z; a0.w += v0.w;
        a1.x += v1.x; a1.y += v1.y; a1.z += v1.z; a1.w += v1.w;
        a2.x += v2.x; a2.y += v2.y; a2.z += v2.z; a2.w += v2.w;
        a3.x += v3.x; a3.y += v3.y; a3.z += v3.z; a3.w += v3.w;
    }
    for (; j < end; j++) {
        int s = g_edgesrc[j];
        float4 v = __ldg(&x4[(size_t)s * 64 + t]);
        a0.x += v.x; a0.y += v.y; a0.z += v.z; a0.w += v.w;
    }
    float e0 = __ldg(&eps[0]);
    float4 self = __ldg(&x4[(size_t)n * 64 + t]);
    float4 o;
    o.x = f2tf32f((1.f + e0) * self.x + ((a0.x + a1.x) + (a2.x + a3.x)));
    o.y = f2tf32f((1.f + e0) * self.y + ((a0.y + a1.y) + (a2.y + a3.y)));
    o.z = f2tf32f((1.f + e0) * self.z + ((a0.z + a1.z) + (a2.z + a3.z)));
    o.w = f2tf32f((1.f + e0) * self.w + ((a0.w + a1.w) + (a2.w + a3.w)));
    ((float4*)g_bufA)[(size_t)n * 64 + t] = o;
}

// ---------------- weight transposes (both in one launch), tf32-rounded --------
// z==0: W1 [256,512] -> g_WT1 [512,256]   (grid 16x8 used)
// z==1: W2 [512,256] -> g_WT2 [256,512]   (grid 8x16 used)
__global__ void k_transpose(const float* __restrict__ W1,
                            const float* __restrict__ W2) {
    __shared__ float t[32][33];
    int which = blockIdx.z;
    const float* W = which ? W2 : W1;
    float* out     = which ? g_WT2 : g_WT1;
    int rows = which ? DIM2 : DIM;    // input rows
    int cols = which ? DIM : DIM2;    // input cols
    int bx = blockIdx.x * 32, by = blockIdx.y * 32;
    if (bx >= cols || by >= rows) return;
    for (int i = threadIdx.y; i < 32; i += 8)
        t[i][threadIdx.x] = W[(size_t)(by + i) * cols + bx + threadIdx.x];
    __syncthreads();
    for (int i = threadIdx.y; i < 32; i += 8)
        out[(size_t)(bx + i) * rows + by + threadIdx.x] =
            f2tf32f(t[threadIdx.x][i]);
}

// ---------------- tf32 mma.sync GEMM, cp.async 2-stage pipeline ----------------
// Inputs are pre-rounded to tf32; mainloop does raw loads (no cvt).
// which==0: A=g_bufA [M,256], B=g_WT1 -> C=g_bufB [M,512], ReLU + tf32 round
// which==1: A=g_bufB [M,512], B=g_WT2 -> C=g_bufA [M,256], fused BN stats
#define GBM 128
#define GBN 128
#define GBK 16
#define SPAD 20     // floats per smem row (16 data + 4 pad); 80B, 16B-aligned

__global__ __launch_bounds__(256, 2)
void k_gemm_tc(int which, const float* __restrict__ bias, int M, int N, int K) {
    const float* A  = which ? g_bufB : g_bufA;
    const float* Bw = which ? g_WT2 : g_WT1;
    float* C        = which ? g_bufA : g_bufB;
    const int do_relu = (which == 0);

    __shared__ float sA[2][GBM * SPAD];   // 2 stages x 10KB
    __shared__ float sB[2][GBM * SPAD];
    __shared__ float s_bns[GBN], s_bnq[GBN];

    int tid = threadIdx.x;
    int wid = tid >> 5;
    int lane = tid & 31;
    int warp_m = wid & 1;        // 2 warps along M (64 rows each)
    int warp_n = wid >> 1;       // 4 warps along N (32 cols each)
    int row0 = blockIdx.y * GBM;
    int col0 = blockIdx.x * GBN;
    int gid = lane >> 2;         // 0..7
    int tig = lane & 3;          // 0..3

    uint32_t saBase = smem_u32(&sA[0][0]);
    uint32_t sbBase = smem_u32(&sB[0][0]);

    float acc[4][4][4];
#pragma unroll
    for (int i = 0; i < 4; i++)
#pragma unroll
        for (int j = 0; j < 4; j++)
#pragma unroll
            for (int c = 0; c < 4; c++) acc[i][j][c] = 0.f;

    auto issue = [&](int kt, int buf) {
#pragma unroll
        for (int i = 0; i < 2; i++) {
            int lin = i * 256 + tid;
            int row = lin >> 2;
            int f = lin & 3;
            uint32_t off = (uint32_t)(buf * GBM * SPAD + row * SPAD + f * 4) * 4u;
            int gr = row0 + row;
            int sz = (gr < M) ? 16 : 0;
            CP_ASYNC16Z(saBase + off, A + (size_t)gr * K + kt + f * 4, sz);
            CP_ASYNC16(sbBase + off, Bw + (size_t)(col0 + row) * K + kt + f * 4);
        }
        CP_COMMIT();
    };

    const uint32_t* uA = (const uint32_t*)&sA[0][0];
    const uint32_t* uB = (const uint32_t*)&sB[0][0];

    const int T = K / GBK;
    issue(0, 0);
    for (int t = 0; t < T; t++) {
        if (t + 1 < T) {
            issue((t + 1) * GBK, (t + 1) & 1);
            CP_WAIT(1);
        } else {
            CP_WAIT(0);
        }
        __syncthreads();
        int bufo = (t & 1) * GBM * SPAD;
#pragma unroll
        for (int kk = 0; kk < GBK; kk += 8) {
            uint32_t af[4][4], bf[4][2];
#pragma unroll
            for (int mt = 0; mt < 4; mt++) {
                int r = warp_m * 64 + mt * 16 + gid;
                af[mt][0] = uA[bufo + r * SPAD + kk + tig];
                af[mt][1] = uA[bufo + (r + 8) * SPAD + kk + tig];
                af[mt][2] = uA[bufo + r * SPAD + kk + tig + 4];
                af[mt][3] = uA[bufo + (r + 8) * SPAD + kk + tig + 4];
            }
#pragma unroll
            for (int nt = 0; nt < 4; nt++) {
                int n = warp_n * 32 + nt * 8 + gid;
                bf[nt][0] = uB[bufo + n * SPAD + kk + tig];
                bf[nt][1] = uB[bufo + n * SPAD + kk + tig + 4];
            }
#pragma unroll
            for (int mt = 0; mt < 4; mt++)
#pragma unroll
                for (int nt = 0; nt < 4; nt++) {
                    asm volatile(
                        "mma.sync.aligned.m16n8k8.row.col.f32.tf32.tf32.f32 "
                        "{%0,%1,%2,%3}, {%4,%5,%6,%7}, {%8,%9}, {%0,%1,%2,%3};"
                        : "+f"(acc[mt][nt][0]), "+f"(acc[mt][nt][1]),
                          "+f"(acc[mt][nt][2]), "+f"(acc[mt][nt][3])
                        : "r"(af[mt][0]), "r"(af[mt][1]), "r"(af[mt][2]), "r"(af[mt][3]),
                          "r"(bf[nt][0]), "r"(bf[nt][1]));
                }
        }
        __syncthreads();
    }

    // epilogue
    if (which == 1) {
        if (tid < GBN) { s_bns[tid] = 0.f; s_bnq[tid] = 0.f; }
        __syncthreads();
    }
    float cs[4][2], cq[4][2];
#pragma unroll
    for (int nt = 0; nt < 4; nt++) {
        cs[nt][0] = cs[nt][1] = cq[nt][0] = cq[nt][1] = 0.f;
        int cb = col0 + warp_n * 32 + nt * 8 + 2 * tig;
        float bv0 = __ldg(&bias[cb]);
        float bv1 = __ldg(&bias[cb + 1]);
#pragma unroll
        for (int mt = 0; mt < 4; mt++) {
            int r = row0 + warp_m * 64 + mt * 16 + gid;
            float v0 = acc[mt][nt][0] + bv0;
            float v1 = acc[mt][nt][1] + bv1;
            float v2 = acc[mt][nt][2] + bv0;
            float v3 = acc[mt][nt][3] + bv1;
            if (do_relu) {
                // h1 feeds GEMM2: round to tf32 here (idempotent w/ MMA cvt)
                v0 = f2tf32f(fmaxf(v0, 0.f));
                v1 = f2tf32f(fmaxf(v1, 0.f));
                v2 = f2tf32f(fmaxf(v2, 0.f));
                v3 = f2tf32f(fmaxf(v3, 0.f));
            }
            if (r < M) {
                *(float2*)&C[(size_t)r * N + cb] = make_float2(v0, v1);
                cs[nt][0] += v0; cq[nt][0] += v0 * v0;
                cs[nt][1] += v1; cq[nt][1] += v1 * v1;
            }
            if (r + 8 < M) {
                *(float2*)&C[(size_t)(r + 8) * N + cb] = make_float2(v2, v3);
                cs[nt][0] += v2; cq[nt][0] += v2 * v2;
                cs[nt][1] += v3; cq[nt][1] += v3 * v3;
            }
        }
    }
    if (which == 1) {
#pragma unroll
        for (int nt = 0; nt < 4; nt++) {
            int cl = warp_n * 32 + nt * 8 + 2 * tig;
            atomicAdd(&s_bns[cl], cs[nt][0]);
            atomicAdd(&s_bns[cl + 1], cs[nt][1]);
            atomicAdd(&s_bnq[cl], cq[nt][0]);
            atomicAdd(&s_bnq[cl + 1], cq[nt][1]);
        }
        __syncthreads();
        if (tid < GBN) {
            atomicAdd(&g_bnsum[col0 + tid], s_bns[tid]);
            atomicAdd(&g_bnsumsq[col0 + tid], s_bnq[tid]);
        }
    }
}

// ---------------- normalize (BN finalize inlined per block) --------------------
// 256 threads/block, 4 float4 per thread
__global__ __launch_bounds__(256) void k_norm(
    float* __restrict__ out,
    const float* __restrict__ gamma, const float* __restrict__ beta) {
    __shared__ float ssc[DIM], ssh[DIM];
    int d = threadIdx.x;
    float mean = g_bnsum[d] * (1.0f / (float)NNODES);
    float var = g_bnsumsq[d] * (1.0f / (float)NNODES) - mean * mean;
    float inv = rsqrtf(var + BN_EPS);
    float sc = inv * __ldg(&gamma[d]);
    ssc[d] = sc;
    ssh[d] = __ldg(&beta[d]) - mean * sc;
    __syncthreads();

    const float4* in4 = (const float4*)g_bufA;
    float4* out4 = (float4*)out;
    int base = (blockIdx.x * 1024 + threadIdx.x);   // float4 index start
#pragma unroll
    for (int it = 0; it < 4; it++) {
        int i = base + it * 256;
        if (i < NNODES * DIM / 4) {
            int dd = (i * 4) & (DIM - 1);
            float4 v = in4[i];
            float4 o;
            o.x = v.x * ssc[dd + 0] + ssh[dd + 0];
            o.y = v.y * ssc[dd + 1] + ssh[dd + 1];
            o.z = v.z * ssc[dd + 2] + ssh[dd + 2];
            o.w = v.w * ssc[dd + 3] + ssh[dd + 3];
            out4[i] = o;
        }
    }
}

// ---------------- launch -------------------------------------------------------
extern "C" void kernel_launch(void* const* d_in, const int* in_sizes, int n_in,
                              void* d_out, int out_size) {
    const float* node_feats = (const float*)d_in[0];
    const void* src         = d_in[1];
    const void* dst         = d_in[2];
    const float* eps        = (const float*)d_in[3];
    const float* W1         = (const float*)d_in[4];
    const float* b1         = (const float*)d_in[5];
    const float* W2         = (const float*)d_in[6];
    const float* b2         = (const float*)d_in[7];
    const float* gamma      = (const float*)d_in[8];
    const float* beta       = (const float*)d_in[9];
    float* out = (float*)d_out;

    // CSR build
    k_zero<<<(NNODES + 255) / 256, 256>>>((const int*)dst);
    k_hist<<<(NEDGES / 2 + 255) / 256, 256>>>(dst);
    k_scan1<<<SCAN_NB, SCAN_CHUNK>>>();
    k_scan2<<<1, 128>>>();
    k_scan3<<<(NNODES + 255) / 256, 256>>>();
    k_scatter<<<(NEDGES / 2 + 255) / 256, 256>>>(src, dst);

    // both weight transposes in one launch (tf32-rounded outputs)
    k_transpose<<<dim3(16, 16, 2), dim3(32, 8)>>>(W1, W2);

    // aggregation -> h0 (g_bufA, tf32-rounded); 4 nodes per block
    k_aggregate<<<(NNODES + 3) / 4, 256>>>(node_feats, eps);

    const int MROWS = (NNODES + GBM - 1) / GBM;   // 782
    // GEMM1: h1 = tf32(relu(h0 @ W1 + b1)) -> g_bufB
    k_gemm_tc<<<dim3(DIM2 / GBN, MROWS), 256>>>(0, b1, NNODES, DIM2, DIM);
    // GEMM2: h2 = h1 @ W2 + b2 -> g_bufA (+ BN stats)
    k_gemm_tc<<<dim3(DIM / GBN, MROWS), 256>>>(1, b2, NNODES, DIM, DIM2);

    // normalize (BN finalize inlined)
    k_norm<<<(NNODES * DIM / 4 + 1023) / 1024, 256>>>(out, gamma, beta);
}

// round 10
// speedup vs baseline: 1.3848x; 1.3848x over previous
#include <cuda_runtime.h>
#include <cuda_fp16.h>
#include <cstdint>

#define NNODES 100000
#define NEDGES 1600000
#define DIM 256
#define DIM2 512
#define BN_EPS 1e-5f

// ---------------- scratch (static device globals; no dynamic alloc) -----------
__device__ int    g_is64;
__device__ int    g_deg[NNODES];
__device__ int    g_rowptr[NNODES + 1];
__device__ int    g_cursor[NNODES];
__device__ int    g_edgesrc[NEDGES];
__device__ __half g_h0[(size_t)NNODES * DIM];      // h0, fp16
__device__ __half g_h1[(size_t)NNODES * DIM2];     // h1, fp16
__device__ float  g_h2[(size_t)NNODES * DIM];      // h2, f32
__device__ __half g_WT1[(size_t)DIM2 * DIM];       // W1^T [512][256] fp16
__device__ __half g_WT2[(size_t)DIM * DIM2];       // W2^T [256][512] fp16
__device__ float  g_bnsum[DIM];
__device__ float  g_bnsumsq[DIM];

#define SCAN_CHUNK 1024
#define SCAN_NB ((NNODES + SCAN_CHUNK - 1) / SCAN_CHUNK)   // 98
__device__ int g_bsum[SCAN_NB];
__device__ int g_boff[SCAN_NB];

// ---------------- helpers ------------------------------------------------------
__device__ __forceinline__ uint32_t smem_u32(const void* p) {
    uint32_t a;
    asm("{ .reg .u64 t; cvta.to.shared.u64 t, %1; cvt.u32.u64 %0, t; }"
        : "=r"(a) : "l"(p));
    return a;
}
#define CP_ASYNC16Z(dst, src, sz) \
    asm volatile("cp.async.cg.shared.global [%0], [%1], 16, %2;" \
                 :: "r"(dst), "l"(src), "r"(sz) : "memory")
#define CP_ASYNC16(dst, src) \
    asm volatile("cp.async.cg.shared.global [%0], [%1], 16;" \
                 :: "r"(dst), "l"(src) : "memory")
#define CP_COMMIT() asm volatile("cp.async.commit_group;" ::: "memory")
#define CP_WAIT(n)  asm volatile("cp.async.wait_group %0;" :: "n"(n) : "memory")

__device__ __forceinline__ int load_idx(const void* p, int e, int is64) {
    return is64 ? (int)((const long long*)p)[e] : ((const int*)p)[e];
}

// ---------------- zero + index-dtype detect ------------------------------------
__global__ void k_zero(const int* __restrict__ dst_raw) {
    int i = blockIdx.x * blockDim.x + threadIdx.x;
    if (i < NNODES) g_deg[i] = 0;
    if (i < DIM) { g_bnsum[i] = 0.f; g_bnsumsq[i] = 0.f; }
    if (i == 0) {
        int is64 = 1;
        for (int k = 0; k < 64; k++)
            if (dst_raw[2 * k + 1] != 0) { is64 = 0; break; }
        g_is64 = is64;
    }
}

// ---------------- CSR build ----------------------------------------------------
__global__ void k_hist(const void* __restrict__ dst) {
    int e0 = (blockIdx.x * blockDim.x + threadIdx.x) * 2;
    int is64 = g_is64;
    if (e0 + 1 < NEDGES) {
        int d0, d1;
        if (is64) {
            longlong2 v = __ldg(&((const longlong2*)dst)[e0 >> 1]);
            d0 = (int)v.x; d1 = (int)v.y;
        } else {
            int2 v = __ldg(&((const int2*)dst)[e0 >> 1]);
            d0 = v.x; d1 = v.y;
        }
        atomicAdd(&g_deg[d0], 1);
        atomicAdd(&g_deg[d1], 1);
    } else if (e0 < NEDGES) {
        atomicAdd(&g_deg[load_idx(dst, e0, is64)], 1);
    }
}
__global__ void k_scan1() {
    __shared__ int sm[SCAN_CHUNK];
    int b = blockIdx.x, tid = threadIdx.x;
    int idx = b * SCAN_CHUNK + tid;
    int v = (idx < NNODES) ? g_deg[idx] : 0;
    sm[tid] = v;
    __syncthreads();
    for (int s = 1; s < SCAN_CHUNK; s <<= 1) {
        int t = (tid >= s) ? sm[tid - s] : 0;
        __syncthreads();
        sm[tid] += t;
        __syncthreads();
    }
    if (idx < NNODES) g_rowptr[idx] = sm[tid] - v;
    if (tid == SCAN_CHUNK - 1) g_bsum[b] = sm[tid];
}
__global__ void k_scan2() {
    __shared__ int sm[128];
    int tid = threadIdx.x;
    int v = (tid < SCAN_NB) ? g_bsum[tid] : 0;
    sm[tid] = v;
    __syncthreads();
    for (int s = 1; s < 128; s <<= 1) {
        int t = (tid >= s) ? sm[tid - s] : 0;
        __syncthreads();
        sm[tid] += t;
        __syncthreads();
    }
    if (tid < SCAN_NB) g_boff[tid] = sm[tid] - v;
    if (tid == 127) g_rowptr[NNODES] = sm[127];
}
__global__ void k_scan3() {
    int i = blockIdx.x * blockDim.x + threadIdx.x;
    if (i < NNODES) {
        int r = g_rowptr[i] + g_boff[i >> 10];
        g_rowptr[i] = r;
        g_cursor[i] = r;
    }
}
__global__ void k_scatter(const void* __restrict__ src,
                          const void* __restrict__ dst) {
    int e0 = (blockIdx.x * blockDim.x + threadIdx.x) * 2;
    int is64 = g_is64;
    if (e0 + 1 < NEDGES) {
        int s0, s1, d0, d1;
        if (is64) {
            longlong2 vs = __ldg(&((const longlong2*)src)[e0 >> 1]);
            longlong2 vd = __ldg(&((const longlong2*)dst)[e0 >> 1]);
            s0 = (int)vs.x; s1 = (int)vs.y;
            d0 = (int)vd.x; d1 = (int)vd.y;
        } else {
            int2 vs = __ldg(&((const int2*)src)[e0 >> 1]);
            int2 vd = __ldg(&((const int2*)dst)[e0 >> 1]);
            s0 = vs.x; s1 = vs.y;
            d0 = vd.x; d1 = vd.y;
        }
        int p0 = atomicAdd(&g_cursor[d0], 1);
        g_edgesrc[p0] = s0;
        int p1 = atomicAdd(&g_cursor[d1], 1);
        g_edgesrc[p1] = s1;
    } else if (e0 < NEDGES) {
        int d = load_idx(dst, e0, is64);
        int pos = atomicAdd(&g_cursor[d], 1);
        g_edgesrc[pos] = load_idx(src, e0, is64);
    }
}

// ---------------- aggregation: h0 = fp16((1+eps)*x + sum x[src]) ---------------
__global__ __launch_bounds__(256) void k_aggregate(
    const float* __restrict__ x, const float* __restrict__ eps) {
    int grp = threadIdx.x >> 6;              // 0..3
    int t = threadIdx.x & 63;                // float4 column
    int n = blockIdx.x * 4 + grp;
    if (n >= NNODES) return;
    const float4* x4 = (const float4*)x;

    int beg = g_rowptr[n];
    int end = g_rowptr[n + 1];
    float4 a0 = make_float4(0.f, 0.f, 0.f, 0.f);
    float4 a1 = make_float4(0.f, 0.f, 0.f, 0.f);
    float4 a2 = make_float4(0.f, 0.f, 0.f, 0.f);
    float4 a3 = make_float4(0.f, 0.f, 0.f, 0.f);
    int j = beg;
    for (; j + 4 <= end; j += 4) {
        int s0 = g_edgesrc[j];
        int s1 = g_edgesrc[j + 1];
        int s2 = g_edgesrc[j + 2];
        int s3 = g_edgesrc[j + 3];
        float4 v0 = __ldg(&x4[(size_t)s0 * 64 + t]);
        float4 v1 = __ldg(&x4[(size_t)s1 * 64 + t]);
        float4 v2 = __ldg(&x4[(size_t)s2 * 64 + t]);
        float4 v3 = __ldg(&x4[(size_t)s3 * 64 + t]);
        a0.x += v0.x; a0.y += v0.y; a0.z += v0.z; a0.w += v0.w;
        a1.x += v1.x; a1.y += v1.y; a1.z += v1.z; a1.w += v1.w;
        a2.x += v2.x; a2.y += v2.y; a2.z += v2.z; a2.w += v2.w;
        a3.x += v3.x; a3.y += v3.y; a3.z += v3.z; a3.w += v3.w;
    }
    for (; j < end; j++) {
        int s = g_edgesrc[j];
        float4 v = __ldg(&x4[(size_t)s * 64 + t]);
        a0.x += v.x; a0.y += v.y; a0.z += v.z; a0.w += v.w;
    }
    float e0 = __ldg(&eps[0]);
    float4 self = __ldg(&x4[(size_t)n * 64 + t]);
    float ox = (1.f + e0) * self.x + ((a0.x + a1.x) + (a2.x + a3.x));
    float oy = (1.f + e0) * self.y + ((a0.y + a1.y) + (a2.y + a3.y));
    float oz = (1.f + e0) * self.z + ((a0.z + a1.z) + (a2.z + a3.z));
    float ow = (1.f + e0) * self.w + ((a0.w + a1.w) + (a2.w + a3.w));
    __half2* o2 = (__half2*)g_h0;
    o2[(size_t)n * 128 + t * 2]     = __floats2half2_rn(ox, oy);
    o2[(size_t)n * 128 + t * 2 + 1] = __floats2half2_rn(oz, ow);
}

// ---------------- weight transposes (one launch), fp16 outputs ----------------
__global__ void k_transpose(const float* __restrict__ W1,
                            const float* __restrict__ W2) {
    __shared__ float t[32][33];
    int which = blockIdx.z;
    const float* W = which ? W2 : W1;
    __half* out    = which ? g_WT2 : g_WT1;
    int rows = which ? DIM2 : DIM;
    int cols = which ? DIM : DIM2;
    int bx = blockIdx.x * 32, by = blockIdx.y * 32;
    if (bx >= cols || by >= rows) return;
    for (int i = threadIdx.y; i < 32; i += 8)
        t[i][threadIdx.x] = W[(size_t)(by + i) * cols + bx + threadIdx.x];
    __syncthreads();
    for (int i = threadIdx.y; i < 32; i += 8)
        out[(size_t)(bx + i) * rows + by + threadIdx.x] =
            __float2half_rn(t[threadIdx.x][i]);
}

// ---------------- fp16 mma.sync m16n8k16 GEMM, cp.async 2-stage ----------------
// which==0: A=g_h0 [M,256]h, B=g_WT1 -> C=g_h1 [M,512]h, ReLU
// which==1: A=g_h1 [M,512]h, B=g_WT2 -> C=g_h2 [M,256]f, fused BN stats
#define GBM 128
#define GBN 128
#define GBK 32       // halfs per k-tile
#define SPAD 20      // uint32 (half2) per smem row: 16 data + 4 pad = 80B

__global__ __launch_bounds__(256, 2)
void k_gemm_tc(int which, const float* __restrict__ bias, int M, int N, int K) {
    const __half* A  = which ? g_h1 : g_h0;
    const __half* Bw = which ? g_WT2 : g_WT1;
    const int do_relu = (which == 0);

    __shared__ uint32_t sA[2][GBM * SPAD];   // 2 stages x 10KB
    __shared__ uint32_t sB[2][GBM * SPAD];
    __shared__ float s_bns[GBN], s_bnq[GBN];

    int tid = threadIdx.x;
    int wid = tid >> 5;
    int lane = tid & 31;
    int warp_m = wid & 1;        // 2 warps along M (64 rows each)
    int warp_n = wid >> 1;       // 4 warps along N (32 cols each)
    int row0 = blockIdx.y * GBM;
    int col0 = blockIdx.x * GBN;
    int gid = lane >> 2;         // 0..7
    int tig = lane & 3;          // 0..3

    uint32_t saBase = smem_u32(&sA[0][0]);
    uint32_t sbBase = smem_u32(&sB[0][0]);

    float acc[4][4][4];
#pragma unroll
    for (int i = 0; i < 4; i++)
#pragma unroll
        for (int j = 0; j < 4; j++)
#pragma unroll
            for (int c = 0; c < 4; c++) acc[i][j][c] = 0.f;

    // one k-tile: 128 rows x 32 halfs (64B) per array = 512 x 16B slots;
    // 256 threads -> 2 slots per thread per array
    auto issue = [&](int kt, int buf) {
#pragma unroll
        for (int i = 0; i < 2; i++) {
            int lin = i * 256 + tid;
            int row = lin >> 2;
            int f = lin & 3;
            uint32_t off = (uint32_t)(buf * GBM * SPAD + row * SPAD + f * 4) * 4u;
            int gr = row0 + row;
            int sz = (gr < M) ? 16 : 0;
            CP_ASYNC16Z(saBase + off, A + (size_t)gr * K + kt + f * 8, sz);
            CP_ASYNC16(sbBase + off, Bw + (size_t)(col0 + row) * K + kt + f * 8);
        }
        CP_COMMIT();
    };

    const uint32_t* uA = &sA[0][0];
    const uint32_t* uB = &sB[0][0];

    const int T = K / GBK;
    issue(0, 0);
    for (int t = 0; t < T; t++) {
        if (t + 1 < T) {
            issue((t + 1) * GBK, (t + 1) & 1);
            CP_WAIT(1);
        } else {
            CP_WAIT(0);
        }
        __syncthreads();
        int bufo = (t & 1) * GBM * SPAD;
#pragma unroll
        for (int kh = 0; kh < GBK / 2; kh += 8) {     // half2 units: 0, 8
            uint32_t af[4][4], bf[4][2];
#pragma unroll
            for (int mt = 0; mt < 4; mt++) {
                int r = warp_m * 64 + mt * 16 + gid;
                af[mt][0] = uA[bufo + r * SPAD + kh + tig];
                af[mt][1] = uA[bufo + (r + 8) * SPAD + kh + tig];
                af[mt][2] = uA[bufo + r * SPAD + kh + tig + 4];
                af[mt][3] = uA[bufo + (r + 8) * SPAD + kh + tig + 4];
            }
#pragma unroll
            for (int nt = 0; nt < 4; nt++) {
                int n = warp_n * 32 + nt * 8 + gid;
                bf[nt][0] = uB[bufo + n * SPAD + kh + tig];
                bf[nt][1] = uB[bufo + n * SPAD + kh + tig + 4];
            }
#pragma unroll
            for (int mt = 0; mt < 4; mt++)
#pragma unroll
                for (int nt = 0; nt < 4; nt++) {
                    asm volatile(
                        "mma.sync.aligned.m16n8k16.row.col.f32.f16.f16.f32 "
                        "{%0,%1,%2,%3}, {%4,%5,%6,%7}, {%8,%9}, {%0,%1,%2,%3};"
                        : "+f"(acc[mt][nt][0]), "+f"(acc[mt][nt][1]),
                          "+f"(acc[mt][nt][2]), "+f"(acc[mt][nt][3])
                        : "r"(af[mt][0]), "r"(af[mt][1]), "r"(af[mt][2]), "r"(af[mt][3]),
                          "r"(bf[nt][0]), "r"(bf[nt][1]));
                }
        }
        __syncthreads();
    }

    // epilogue
    if (which == 1) {
        if (tid < GBN) { s_bns[tid] = 0.f; s_bnq[tid] = 0.f; }
        __syncthreads();
    }
    float cs[4][2], cq[4][2];
#pragma unroll
    for (int nt = 0; nt < 4; nt++) {
        cs[nt][0] = cs[nt][1] = cq[nt][0] = cq[nt][1] = 0.f;
        int cb = col0 + warp_n * 32 + nt * 8 + 2 * tig;
        float bv0 = __ldg(&bias[cb]);
        float bv1 = __ldg(&bias[cb + 1]);
#pragma unroll
        for (int mt = 0; mt < 4; mt++) {
            int r = row0 + warp_m * 64 + mt * 16 + gid;
            float v0 = acc[mt][nt][0] + bv0;
            float v1 = acc[mt][nt][1] + bv1;
            float v2 = acc[mt][nt][2] + bv0;
            float v3 = acc[mt][nt][3] + bv1;
            if (do_relu) {
                // h1 (fp16) path
                v0 = fmaxf(v0, 0.f); v1 = fmaxf(v1, 0.f);
                v2 = fmaxf(v2, 0.f); v3 = fmaxf(v3, 0.f);
                if (r < M)
                    *(__half2*)&g_h1[(size_t)r * N + cb] = __floats2half2_rn(v0, v1);
                if (r + 8 < M)
                    *(__half2*)&g_h1[(size_t)(r + 8) * N + cb] = __floats2half2_rn(v2, v3);
            } else {
                if (r < M) {
                    *(float2*)&g_h2[(size_t)r * N + cb] = make_float2(v0, v1);
                    cs[nt][0] += v0; cq[nt][0] += v0 * v0;
                    cs[nt][1] += v1; cq[nt][1] += v1 * v1;
                }
                if (r + 8 < M) {
                    *(float2*)&g_h2[(size_t)(r + 8) * N + cb] = make_float2(v2, v3);
                    cs[nt][0] += v2; cq[nt][0] += v2 * v2;
                    cs[nt][1] += v3; cq[nt][1] += v3 * v3;
                }
            }
        }
    }
    if (which == 1) {
#pragma unroll
        for (int nt = 0; nt < 4; nt++) {
            int cl = warp_n * 32 + nt * 8 + 2 * tig;
            atomicAdd(&s_bns[cl], cs[nt][0]);
            atomicAdd(&s_bns[cl + 1], cs[nt][1]);
            atomicAdd(&s_bnq[cl], cq[nt][0]);
            atomicAdd(&s_bnq[cl + 1], cq[nt][1]);
        }
        __syncthreads();
        if (tid < GBN) {
            atomicAdd(&g_bnsum[col0 + tid], s_bns[tid]);
            atomicAdd(&g_bnsumsq[col0 + tid], s_bnq[tid]);
        }
    }
}

// ---------------- normalize (BN finalize inlined per block) --------------------
__global__ __launch_bounds__(256) void k_norm(
    float* __restrict__ out,
    const float* __restrict__ gamma, const float* __restrict__ beta) {
    __shared__ float ssc[DIM], ssh[DIM];
    int d = threadIdx.x;
    float mean = g_bnsum[d] * (1.0f / (float)NNODES);
    float var = g_bnsumsq[d] * (1.0f / (float)NNODES) - mean * mean;
    float inv = rsqrtf(var + BN_EPS);
    float sc = inv * __ldg(&gamma[d]);
    ssc[d] = sc;
    ssh[d] = __ldg(&beta[d]) - mean * sc;
    __syncthreads();

    const float4* in4 = (const float4*)g_h2;
    float4* out4 = (float4*)out;
    int base = (blockIdx.x * 1024 + threadIdx.x);
#pragma unroll
    for (int it = 0; it < 4; it++) {
        int i = base + it * 256;
        if (i < NNODES * DIM / 4) {
            int dd = (i * 4) & (DIM - 1);
            float4 v = in4[i];
            float4 o;
            o.x = v.x * ssc[dd + 0] + ssh[dd + 0];
            o.y = v.y * ssc[dd + 1] + ssh[dd + 1];
            o.z = v.z * ssc[dd + 2] + ssh[dd + 2];
            o.w = v.w * ssc[dd + 3] + ssh[dd + 3];
            out4[i] = o;
        }
    }
}

// ---------------- launch -------------------------------------------------------
extern "C" void kernel_launch(void* const* d_in, const int* in_sizes, int n_in,
                              void* d_out, int out_size) {
    const float* node_feats = (const float*)d_in[0];
    const void* src         = d_in[1];
    const void* dst         = d_in[2];
    const float* eps        = (const float*)d_in[3];
    const float* W1         = (const float*)d_in[4];
    const float* b1         = (const float*)d_in[5];
    const float* W2         = (const float*)d_in[6];
    const float* b2         = (const float*)d_in[7];
    const float* gamma      = (const float*)d_in[8];
    const float* beta       = (const float*)d_in[9];
    float* out = (float*)d_out;

    // CSR build
    k_zero<<<(NNODES + 255) / 256, 256>>>((const int*)dst);
    k_hist<<<(NEDGES / 2 + 255) / 256, 256>>>(dst);
    k_scan1<<<SCAN_NB, SCAN_CHUNK>>>();
    k_scan2<<<1, 128>>>();
    k_scan3<<<(NNODES + 255) / 256, 256>>>();
    k_scatter<<<(NEDGES / 2 + 255) / 256, 256>>>(src, dst);

    // weight transposes (fp16 outputs)
    k_transpose<<<dim3(16, 16, 2), dim3(32, 8)>>>(W1, W2);

    // aggregation -> h0 fp16; 4 nodes per block
    k_aggregate<<<(NNODES + 3) / 4, 256>>>(node_feats, eps);

    const int MROWS = (NNODES + GBM - 1) / GBM;   // 782
    // GEMM1: h1 = fp16(relu(h0 @ W1 + b1))
    k_gemm_tc<<<dim3(DIM2 / GBN, MROWS), 256>>>(0, b1, NNODES, DIM2, DIM);
    // GEMM2: h2 = h1 @ W2 + b2 (f32) + BN stats
    k_gemm_tc<<<dim3(DIM / GBN, MROWS), 256>>>(1, b2, NNODES, DIM, DIM2);

    // normalize (BN finalize inlined)
    k_norm<<<(NNODES * DIM / 4 + 1023) / 1024, 256>>>(out, gamma, beta);
}

// round 11
// speedup vs baseline: 1.5551x; 1.1230x over previous
#include <cuda_runtime.h>
#include <cuda_fp16.h>
#include <cstdint>

#define NNODES 100000
#define NEDGES 1600000
#define DIM 256
#define DIM2 512
#define BN_EPS 1e-5f

// ---------------- scratch (static device globals; no dynamic alloc) -----------
__device__ int    g_is64;
__device__ int    g_deg[NNODES];
__device__ int    g_rowptr[NNODES + 1];
__device__ int    g_cursor[NNODES];
__device__ int    g_edgesrc[NEDGES];
__device__ __half g_xh[(size_t)NNODES * DIM];      // x, fp16 mirror
__device__ __half g_h0[(size_t)NNODES * DIM];      // h0, fp16
__device__ __half g_h1[(size_t)NNODES * DIM2];     // h1, fp16
__device__ float  g_h2[(size_t)NNODES * DIM];      // h2, f32
__device__ __half g_WT1[(size_t)DIM2 * DIM];       // W1^T [512][256] fp16
__device__ __half g_WT2[(size_t)DIM * DIM2];       // W2^T [256][512] fp16
__device__ float  g_bnsum[DIM];
__device__ float  g_bnsumsq[DIM];

#define SCAN_CHUNK 1024
#define SCAN_NB ((NNODES + SCAN_CHUNK - 1) / SCAN_CHUNK)   // 98
__device__ int g_bsum[SCAN_NB];
__device__ int g_boff[SCAN_NB];

// ---------------- helpers ------------------------------------------------------
__device__ __forceinline__ uint32_t smem_u32(const void* p) {
    uint32_t a;
    asm("{ .reg .u64 t; cvta.to.shared.u64 t, %1; cvt.u32.u64 %0, t; }"
        : "=r"(a) : "l"(p));
    return a;
}
#define CP_ASYNC16Z(dst, src, sz) \
    asm volatile("cp.async.cg.shared.global [%0], [%1], 16, %2;" \
                 :: "r"(dst), "l"(src), "r"(sz) : "memory")
#define CP_ASYNC16(dst, src) \
    asm volatile("cp.async.cg.shared.global [%0], [%1], 16;" \
                 :: "r"(dst), "l"(src) : "memory")
#define CP_COMMIT() asm volatile("cp.async.commit_group;" ::: "memory")
#define CP_WAIT(n)  asm volatile("cp.async.wait_group %0;" :: "n"(n) : "memory")

__device__ __forceinline__ int load_idx(const void* p, int e, int is64) {
    return is64 ? (int)((const long long*)p)[e] : ((const int*)p)[e];
}
__device__ __forceinline__ void acc8(float* a, uint4 v) {
    float2 f0 = __half22float2(*(__half2*)&v.x);
    float2 f1 = __half22float2(*(__half2*)&v.y);
    float2 f2 = __half22float2(*(__half2*)&v.z);
    float2 f3 = __half22float2(*(__half2*)&v.w);
    a[0] += f0.x; a[1] += f0.y; a[2] += f1.x; a[3] += f1.y;
    a[4] += f2.x; a[5] += f2.y; a[6] += f3.x; a[7] += f3.y;
}

// ---------------- zero + index-dtype detect ------------------------------------
__global__ void k_zero(const int* __restrict__ dst_raw) {
    int i = blockIdx.x * blockDim.x + threadIdx.x;
    if (i < NNODES) g_deg[i] = 0;
    if (i < DIM) { g_bnsum[i] = 0.f; g_bnsumsq[i] = 0.f; }
    if (i == 0) {
        int is64 = 1;
        for (int k = 0; k < 64; k++)
            if (dst_raw[2 * k + 1] != 0) { is64 = 0; break; }
        g_is64 = is64;
    }
}

// ---------------- x -> fp16 mirror ---------------------------------------------
__global__ __launch_bounds__(256) void k_xhalf(const float* __restrict__ x) {
    int i = blockIdx.x * blockDim.x + threadIdx.x;   // over N*DIM/8
    if (i >= NNODES * DIM / 8) return;
    const float4* x4 = (const float4*)x;
    float4 v0 = __ldg(&x4[i * 2]);
    float4 v1 = __ldg(&x4[i * 2 + 1]);
    uint4 o;
    *(__half2*)&o.x = __floats2half2_rn(v0.x, v0.y);
    *(__half2*)&o.y = __floats2half2_rn(v0.z, v0.w);
    *(__half2*)&o.z = __floats2half2_rn(v1.x, v1.y);
    *(__half2*)&o.w = __floats2half2_rn(v1.z, v1.w);
    ((uint4*)g_xh)[i] = o;
}

// ---------------- CSR build ----------------------------------------------------
__global__ void k_hist(const void* __restrict__ dst) {
    int e0 = (blockIdx.x * blockDim.x + threadIdx.x) * 2;
    int is64 = g_is64;
    if (e0 + 1 < NEDGES) {
        int d0, d1;
        if (is64) {
            longlong2 v = __ldg(&((const longlong2*)dst)[e0 >> 1]);
            d0 = (int)v.x; d1 = (int)v.y;
        } else {
            int2 v = __ldg(&((const int2*)dst)[e0 >> 1]);
            d0 = v.x; d1 = v.y;
        }
        atomicAdd(&g_deg[d0], 1);
        atomicAdd(&g_deg[d1], 1);
    } else if (e0 < NEDGES) {
        atomicAdd(&g_deg[load_idx(dst, e0, is64)], 1);
    }
}
__global__ void k_scan1() {
    __shared__ int sm[SCAN_CHUNK];
    int b = blockIdx.x, tid = threadIdx.x;
    int idx = b * SCAN_CHUNK + tid;
    int v = (idx < NNODES) ? g_deg[idx] : 0;
    sm[tid] = v;
    __syncthreads();
    for (int s = 1; s < SCAN_CHUNK; s <<= 1) {
        int t = (tid >= s) ? sm[tid - s] : 0;
        __syncthreads();
        sm[tid] += t;
        __syncthreads();
    }
    if (idx < NNODES) g_rowptr[idx] = sm[tid] - v;
    if (tid == SCAN_CHUNK - 1) g_bsum[b] = sm[tid];
}
__global__ void k_scan2() {
    __shared__ int sm[128];
    int tid = threadIdx.x;
    int v = (tid < SCAN_NB) ? g_bsum[tid] : 0;
    sm[tid] = v;
    __syncthreads();
    for (int s = 1; s < 128; s <<= 1) {
        int t = (tid >= s) ? sm[tid - s] : 0;
        __syncthreads();
        sm[tid] += t;
        __syncthreads();
    }
    if (tid < SCAN_NB) g_boff[tid] = sm[tid] - v;
    if (tid == 127) g_rowptr[NNODES] = sm[127];
}
__global__ void k_scan3() {
    int i = blockIdx.x * blockDim.x + threadIdx.x;
    if (i < NNODES) {
        int r = g_rowptr[i] + g_boff[i >> 10];
        g_rowptr[i] = r;
        g_cursor[i] = r;
    }
}
__global__ void k_scatter(const void* __restrict__ src,
                          const void* __restrict__ dst) {
    int e0 = (blockIdx.x * blockDim.x + threadIdx.x) * 2;
    int is64 = g_is64;
    if (e0 + 1 < NEDGES) {
        int s0, s1, d0, d1;
        if (is64) {
            longlong2 vs = __ldg(&((const longlong2*)src)[e0 >> 1]);
            longlong2 vd = __ldg(&((const longlong2*)dst)[e0 >> 1]);
            s0 = (int)vs.x; s1 = (int)vs.y;
            d0 = (int)vd.x; d1 = (int)vd.y;
        } else {
            int2 vs = __ldg(&((const int2*)src)[e0 >> 1]);
            int2 vd = __ldg(&((const int2*)dst)[e0 >> 1]);
            s0 = vs.x; s1 = vs.y;
            d0 = vd.x; d1 = vd.y;
        }
        int p0 = atomicAdd(&g_cursor[d0], 1);
        g_edgesrc[p0] = s0;
        int p1 = atomicAdd(&g_cursor[d1], 1);
        g_edgesrc[p1] = s1;
    } else if (e0 < NEDGES) {
        int d = load_idx(dst, e0, is64);
        int pos = atomicAdd(&g_cursor[d], 1);
        g_edgesrc[pos] = load_idx(src, e0, is64);
    }
}

// ---------------- aggregation: h0 = fp16((1+eps)*x + sum xh[src]) --------------
// 1 warp per node, 8 nodes/block; lane covers 8 halfs (16B); 4-edge unroll
__global__ __launch_bounds__(256) void k_aggregate(
    const float* __restrict__ x, const float* __restrict__ eps) {
    int warp = threadIdx.x >> 5;             // 0..7
    int t = threadIdx.x & 31;                // 16B chunk within row
    int n = blockIdx.x * 8 + warp;
    if (n >= NNODES) return;
    const uint4* xh4 = (const uint4*)g_xh;   // 32 uint4 per row

    int beg = g_rowptr[n];
    int end = g_rowptr[n + 1];
    float a[8] = {0.f, 0.f, 0.f, 0.f, 0.f, 0.f, 0.f, 0.f};
    int j = beg;
    for (; j + 4 <= end; j += 4) {
        int s0 = g_edgesrc[j];
        int s1 = g_edgesrc[j + 1];
        int s2 = g_edgesrc[j + 2];
        int s3 = g_edgesrc[j + 3];
        uint4 v0 = __ldg(&xh4[(size_t)s0 * 32 + t]);
        uint4 v1 = __ldg(&xh4[(size_t)s1 * 32 + t]);
        uint4 v2 = __ldg(&xh4[(size_t)s2 * 32 + t]);
        uint4 v3 = __ldg(&xh4[(size_t)s3 * 32 + t]);
        acc8(a, v0); acc8(a, v1); acc8(a, v2); acc8(a, v3);
    }
    for (; j < end; j++) {
        uint4 v = __ldg(&xh4[(size_t)g_edgesrc[j] * 32 + t]);
        acc8(a, v);
    }
    float e0 = 1.f + __ldg(&eps[0]);
    const float4* x4 = (const float4*)x;
    float4 s0 = __ldg(&x4[(size_t)n * 64 + t * 2]);
    float4 s1 = __ldg(&x4[(size_t)n * 64 + t * 2 + 1]);
    uint4 o;
    *(__half2*)&o.x = __floats2half2_rn(e0 * s0.x + a[0], e0 * s0.y + a[1]);
    *(__half2*)&o.y = __floats2half2_rn(e0 * s0.z + a[2], e0 * s0.w + a[3]);
    *(__half2*)&o.z = __floats2half2_rn(e0 * s1.x + a[4], e0 * s1.y + a[5]);
    *(__half2*)&o.w = __floats2half2_rn(e0 * s1.z + a[6], e0 * s1.w + a[7]);
    ((uint4*)g_h0)[(size_t)n * 32 + t] = o;
}

// ---------------- weight transposes (one launch), fp16 outputs ----------------
__global__ void k_transpose(const float* __restrict__ W1,
                            const float* __restrict__ W2) {
    __shared__ float t[32][33];
    int which = blockIdx.z;
    const float* W = which ? W2 : W1;
    __half* out    = which ? g_WT2 : g_WT1;
    int rows = which ? DIM2 : DIM;
    int cols = which ? DIM : DIM2;
    int bx = blockIdx.x * 32, by = blockIdx.y * 32;
    if (bx >= cols || by >= rows) return;
    for (int i = threadIdx.y; i < 32; i += 8)
        t[i][threadIdx.x] = W[(size_t)(by + i) * cols + bx + threadIdx.x];
    __syncthreads();
    for (int i = threadIdx.y; i < 32; i += 8)
        out[(size_t)(bx + i) * rows + by + threadIdx.x] =
            __float2half_rn(t[threadIdx.x][i]);
}

// ---------------- fp16 mma.sync m16n8k16 GEMM, cp.async 2-stage ----------------
// which==0: A=g_h0 [M,256]h, B=g_WT1 -> C=g_h1 [M,512]h, ReLU
// which==1: A=g_h1 [M,512]h, B=g_WT2 -> C=g_h2 [M,256]f, fused BN stats
#define GBM 128
#define GBN 128
#define GBK 32       // halfs per k-tile
#define SPAD 20      // uint32 (half2) per smem row: 16 data + 4 pad = 80B

__global__ __launch_bounds__(256, 2)
void k_gemm_tc(int which, const float* __restrict__ bias, int M, int N, int K) {
    const __half* A  = which ? g_h1 : g_h0;
    const __half* Bw = which ? g_WT2 : g_WT1;
    const int do_relu = (which == 0);

    __shared__ uint32_t sA[2][GBM * SPAD];   // 2 stages x 10KB
    __shared__ uint32_t sB[2][GBM * SPAD];
    __shared__ float s_bns[GBN], s_bnq[GBN];

    int tid = threadIdx.x;
    int wid = tid >> 5;
    int lane = tid & 31;
    int warp_m = wid & 1;        // 2 warps along M (64 rows each)
    int warp_n = wid >> 1;       // 4 warps along N (32 cols each)
    int row0 = blockIdx.y * GBM;
    int col0 = blockIdx.x * GBN;
    int gid = lane >> 2;         // 0..7
    int tig = lane & 3;          // 0..3

    uint32_t saBase = smem_u32(&sA[0][0]);
    uint32_t sbBase = smem_u32(&sB[0][0]);

    float acc[4][4][4];
#pragma unroll
    for (int i = 0; i < 4; i++)
#pragma unroll
        for (int j = 0; j < 4; j++)
#pragma unroll
            for (int c = 0; c < 4; c++) acc[i][j][c] = 0.f;

    auto issue = [&](int kt, int buf) {
#pragma unroll
        for (int i = 0; i < 2; i++) {
            int lin = i * 256 + tid;
            int row = lin >> 2;
            int f = lin & 3;
            uint32_t off = (uint32_t)(buf * GBM * SPAD + row * SPAD + f * 4) * 4u;
            int gr = row0 + row;
            int sz = (gr < M) ? 16 : 0;
            CP_ASYNC16Z(saBase + off, A + (size_t)gr * K + kt + f * 8, sz);
            CP_ASYNC16(sbBase + off, Bw + (size_t)(col0 + row) * K + kt + f * 8);
        }
        CP_COMMIT();
    };

    const uint32_t* uA = &sA[0][0];
    const uint32_t* uB = &sB[0][0];

    const int T = K / GBK;
    issue(0, 0);
    for (int t = 0; t < T; t++) {
        if (t + 1 < T) {
            issue((t + 1) * GBK, (t + 1) & 1);
            CP_WAIT(1);
        } else {
            CP_WAIT(0);
        }
        __syncthreads();
        int bufo = (t & 1) * GBM * SPAD;
#pragma unroll
        for (int kh = 0; kh < GBK / 2; kh += 8) {     // half2 units: 0, 8
            uint32_t af[4][4], bf[4][2];
#pragma unroll
            for (int mt = 0; mt < 4; mt++) {
                int r = warp_m * 64 + mt * 16 + gid;
                af[mt][0] = uA[bufo + r * SPAD + kh + tig];
                af[mt][1] = uA[bufo + (r + 8) * SPAD + kh + tig];
                af[mt][2] = uA[bufo + r * SPAD + kh + tig + 4];
                af[mt][3] = uA[bufo + (r + 8) * SPAD + kh + tig + 4];
            }
#pragma unroll
            for (int nt = 0; nt < 4; nt++) {
                int n = warp_n * 32 + nt * 8 + gid;
                bf[nt][0] = uB[bufo + n * SPAD + kh + tig];
                bf[nt][1] = uB[bufo + n * SPAD + kh + tig + 4];
            }
#pragma unroll
            for (int mt = 0; mt < 4; mt++)
#pragma unroll
                for (int nt = 0; nt < 4; nt++) {
                    asm volatile(
                        "mma.sync.aligned.m16n8k16.row.col.f32.f16.f16.f32 "
                        "{%0,%1,%2,%3}, {%4,%5,%6,%7}, {%8,%9}, {%0,%1,%2,%3};"
                        : "+f"(acc[mt][nt][0]), "+f"(acc[mt][nt][1]),
                          "+f"(acc[mt][nt][2]), "+f"(acc[mt][nt][3])
                        : "r"(af[mt][0]), "r"(af[mt][1]), "r"(af[mt][2]), "r"(af[mt][3]),
                          "r"(bf[nt][0]), "r"(bf[nt][1]));
                }
        }
        __syncthreads();
    }

    // epilogue
    if (which == 1) {
        if (tid < GBN) { s_bns[tid] = 0.f; s_bnq[tid] = 0.f; }
        __syncthreads();
    }
    float cs[4][2], cq[4][2];
#pragma unroll
    for (int nt = 0; nt < 4; nt++) {
        cs[nt][0] = cs[nt][1] = cq[nt][0] = cq[nt][1] = 0.f;
        int cb = col0 + warp_n * 32 + nt * 8 + 2 * tig;
        float bv0 = __ldg(&bias[cb]);
        float bv1 = __ldg(&bias[cb + 1]);
#pragma unroll
        for (int mt = 0; mt < 4; mt++) {
            int r = row0 + warp_m * 64 + mt * 16 + gid;
            float v0 = acc[mt][nt][0] + bv0;
            float v1 = acc[mt][nt][1] + bv1;
            float v2 = acc[mt][nt][2] + bv0;
            float v3 = acc[mt][nt][3] + bv1;
            if (do_relu) {
                v0 = fmaxf(v0, 0.f); v1 = fmaxf(v1, 0.f);
                v2 = fmaxf(v2, 0.f); v3 = fmaxf(v3, 0.f);
                if (r < M)
                    *(__half2*)&g_h1[(size_t)r * N + cb] = __floats2half2_rn(v0, v1);
                if (r + 8 < M)
                    *(__half2*)&g_h1[(size_t)(r + 8) * N + cb] = __floats2half2_rn(v2, v3);
            } else {
                if (r < M) {
                    *(float2*)&g_h2[(size_t)r * N + cb] = make_float2(v0, v1);
                    cs[nt][0] += v0; cq[nt][0] += v0 * v0;
                    cs[nt][1] += v1; cq[nt][1] += v1 * v1;
                }
                if (r + 8 < M) {
                    *(float2*)&g_h2[(size_t)(r + 8) * N + cb] = make_float2(v2, v3);
                    cs[nt][0] += v2; cq[nt][0] += v2 * v2;
                    cs[nt][1] += v3; cq[nt][1] += v3 * v3;
                }
            }
        }
    }
    if (which == 1) {
#pragma unroll
        for (int nt = 0; nt < 4; nt++) {
            int cl = warp_n * 32 + nt * 8 + 2 * tig;
            atomicAdd(&s_bns[cl], cs[nt][0]);
            atomicAdd(&s_bns[cl + 1], cs[nt][1]);
            atomicAdd(&s_bnq[cl], cq[nt][0]);
            atomicAdd(&s_bnq[cl + 1], cq[nt][1]);
        }
        __syncthreads();
        if (tid < GBN) {
            atomicAdd(&g_bnsum[col0 + tid], s_bns[tid]);
            atomicAdd(&g_bnsumsq[col0 + tid], s_bnq[tid]);
        }
    }
}

// ---------------- normalize (BN finalize inlined per block) --------------------
__global__ __launch_bounds__(256) void k_norm(
    float* __restrict__ out,
    const float* __restrict__ gamma, const float* __restrict__ beta) {
    __shared__ float ssc[DIM], ssh[DIM];
    int d = threadIdx.x;
    float mean = g_bnsum[d] * (1.0f / (float)NNODES);
    float var = g_bnsumsq[d] * (1.0f / (float)NNODES) - mean * mean;
    float inv = rsqrtf(var + BN_EPS);
    float sc = inv * __ldg(&gamma[d]);
    ssc[d] = sc;
    ssh[d] = __ldg(&beta[d]) - mean * sc;
    __syncthreads();

    const float4* in4 = (const float4*)g_h2;
    float4* out4 = (float4*)out;
    int base = (blockIdx.x * 1024 + threadIdx.x);
#pragma unroll
    for (int it = 0; it < 4; it++) {
        int i = base + it * 256;
        if (i < NNODES * DIM / 4) {
            int dd = (i * 4) & (DIM - 1);
            float4 v = in4[i];
            float4 o;
            o.x = v.x * ssc[dd + 0] + ssh[dd + 0];
            o.y = v.y * ssc[dd + 1] + ssh[dd + 1];
            o.z = v.z * ssc[dd + 2] + ssh[dd + 2];
            o.w = v.w * ssc[dd + 3] + ssh[dd + 3];
            out4[i] = o;
        }
    }
}

// ---------------- launch -------------------------------------------------------
extern "C" void kernel_launch(void* const* d_in, const int* in_sizes, int n_in,
                              void* d_out, int out_size) {
    const float* node_feats = (const float*)d_in[0];
    const void* src         = d_in[1];
    const void* dst         = d_in[2];
    const float* eps        = (const float*)d_in[3];
    const float* W1         = (const float*)d_in[4];
    const float* b1         = (const float*)d_in[5];
    const float* W2         = (const float*)d_in[6];
    const float* b2         = (const float*)d_in[7];
    const float* gamma      = (const float*)d_in[8];
    const float* beta       = (const float*)d_in[9];
    float* out = (float*)d_out;

    // CSR build + fp16 mirror of x (independent work interleaved)
    k_zero<<<(NNODES + 255) / 256, 256>>>((const int*)dst);
    k_xhalf<<<(NNODES * DIM / 8 + 255) / 256, 256>>>(node_feats);
    k_hist<<<(NEDGES / 2 + 255) / 256, 256>>>(dst);
    k_scan1<<<SCAN_NB, SCAN_CHUNK>>>();
    k_scan2<<<1, 128>>>();
    k_scan3<<<(NNODES + 255) / 256, 256>>>();
    k_scatter<<<(NEDGES / 2 + 255) / 256, 256>>>(src, dst);

    // weight transposes (fp16 outputs)
    k_transpose<<<dim3(16, 16, 2), dim3(32, 8)>>>(W1, W2);

    // aggregation -> h0 fp16; 8 nodes per block (1 warp each)
    k_aggregate<<<(NNODES + 7) / 8, 256>>>(node_feats, eps);

    const int MROWS = (NNODES + GBM - 1) / GBM;   // 782
    // GEMM1: h1 = fp16(relu(h0 @ W1 + b1))
    k_gemm_tc<<<dim3(DIM2 / GBN, MROWS), 256>>>(0, b1, NNODES, DIM2, DIM);
    // GEMM2: h2 = h1 @ W2 + b2 (f32) + BN stats
    k_gemm_tc<<<dim3(DIM / GBN, MROWS), 256>>>(1, b2, NNODES, DIM, DIM2);

    // normalize (BN finalize inlined)
    k_norm<<<(NNODES * DIM / 4 + 1023) / 1024, 256>>>(out, gamma, beta);
}

// round 12
// speedup vs baseline: 1.5917x; 1.0235x over previous
#include <cuda_runtime.h>
#include <cuda_fp16.h>
#include <cstdint>

#define NNODES 100000
#define NEDGES 1600000
#define DIM 256
#define DIM2 512
#define BN_EPS 1e-5f

// ---------------- scratch (static device globals; no dynamic alloc) -----------
__device__ int    g_is64;
__device__ int    g_deg[NNODES];
__device__ int    g_rowptr[NNODES + 1];
__device__ int    g_cursor[NNODES];
__device__ int    g_edgesrc[NEDGES];
__device__ __half g_xh[(size_t)NNODES * DIM];      // x, fp16 mirror
__device__ __half g_h0[(size_t)NNODES * DIM];      // h0, fp16
__device__ __half g_h1[(size_t)NNODES * DIM2];     // h1, fp16
__device__ float  g_h2[(size_t)NNODES * DIM];      // h2, f32
__device__ __half g_WT1[(size_t)DIM2 * DIM];       // W1^T [512][256] fp16
__device__ __half g_WT2[(size_t)DIM * DIM2];       // W2^T [256][512] fp16
__device__ float  g_bnsum[DIM];
__device__ float  g_bnsumsq[DIM];

#define SCAN_CHUNK 1024
#define SCAN_NB ((NNODES + SCAN_CHUNK - 1) / SCAN_CHUNK)   // 98
__device__ int g_bsum[SCAN_NB];
__device__ int g_boff[SCAN_NB];

// ---------------- helpers ------------------------------------------------------
__device__ __forceinline__ uint32_t smem_u32(const void* p) {
    uint32_t a;
    asm("{ .reg .u64 t; cvta.to.shared.u64 t, %1; cvt.u32.u64 %0, t; }"
        : "=r"(a) : "l"(p));
    return a;
}
#define CP_ASYNC16Z(dst, src, sz) \
    asm volatile("cp.async.cg.shared.global [%0], [%1], 16, %2;" \
                 :: "r"(dst), "l"(src), "r"(sz) : "memory")
#define CP_ASYNC16(dst, src) \
    asm volatile("cp.async.cg.shared.global [%0], [%1], 16;" \
                 :: "r"(dst), "l"(src) : "memory")
#define CP_COMMIT() asm volatile("cp.async.commit_group;" ::: "memory")
#define CP_WAIT(n)  asm volatile("cp.async.wait_group %0;" :: "n"(n) : "memory")

__device__ __forceinline__ int load_idx(const void* p, int e, int is64) {
    return is64 ? (int)((const long long*)p)[e] : ((const int*)p)[e];
}
__device__ __forceinline__ void acc8(float* a, uint4 v) {
    float2 f0 = __half22float2(*(__half2*)&v.x);
    float2 f1 = __half22float2(*(__half2*)&v.y);
    float2 f2 = __half22float2(*(__half2*)&v.z);
    float2 f3 = __half22float2(*(__half2*)&v.w);
    a[0] += f0.x; a[1] += f0.y; a[2] += f1.x; a[3] += f1.y;
    a[4] += f2.x; a[5] += f2.y; a[6] += f3.x; a[7] += f3.y;
}

// ---------------- fused prep: xhalf | zero+detect | transposes -----------------
#define XH_BLOCKS (NNODES * DIM / 8 / 256)               // 12500
#define ZERO_BLOCKS ((NNODES + 255) / 256)               // 391
#define PREP_BLOCKS (XH_BLOCKS + ZERO_BLOCKS + 512)

__global__ __launch_bounds__(256) void k_prep(
    const float* __restrict__ x, const float* __restrict__ W1,
    const float* __restrict__ W2, const int* __restrict__ dst_raw) {
    int b = blockIdx.x;
    int tid = threadIdx.x;
    if (b < XH_BLOCKS) {
        // x -> fp16 mirror
        int i = b * 256 + tid;
        const float4* x4 = (const float4*)x;
        float4 v0 = __ldg(&x4[i * 2]);
        float4 v1 = __ldg(&x4[i * 2 + 1]);
        uint4 o;
        *(__half2*)&o.x = __floats2half2_rn(v0.x, v0.y);
        *(__half2*)&o.y = __floats2half2_rn(v0.z, v0.w);
        *(__half2*)&o.z = __floats2half2_rn(v1.x, v1.y);
        *(__half2*)&o.w = __floats2half2_rn(v1.z, v1.w);
        ((uint4*)g_xh)[i] = o;
    } else if (b < XH_BLOCKS + ZERO_BLOCKS) {
        int i = (b - XH_BLOCKS) * 256 + tid;
        if (i < NNODES) g_deg[i] = 0;
        if (i < DIM) { g_bnsum[i] = 0.f; g_bnsumsq[i] = 0.f; }
        if (i == 0) {
            int is64 = 1;
            for (int k = 0; k < 64; k++)
                if (dst_raw[2 * k + 1] != 0) { is64 = 0; break; }
            g_is64 = is64;
        }
    } else {
        // weight transposes, fp16 outputs
        __shared__ float t[32][33];
        int w = b - XH_BLOCKS - ZERO_BLOCKS;   // 0..511
        int which = w >> 8;
        int rem = w & 255;
        int bx = (rem & 15) * 32, by = (rem >> 4) * 32;
        const float* W = which ? W2 : W1;
        __half* outp   = which ? g_WT2 : g_WT1;
        int rows = which ? DIM2 : DIM;
        int cols = which ? DIM : DIM2;
        if (bx >= cols || by >= rows) return;
        int tx = tid & 31, ty = tid >> 5;      // 32 x 8
        for (int i = ty; i < 32; i += 8)
            t[i][tx] = W[(size_t)(by + i) * cols + bx + tx];
        __syncthreads();
        for (int i = ty; i < 32; i += 8)
            outp[(size_t)(bx + i) * rows + by + tx] = __float2half_rn(t[tx][i]);
    }
}

// ---------------- CSR build ----------------------------------------------------
__global__ void k_hist(const void* __restrict__ dst) {
    int e0 = (blockIdx.x * blockDim.x + threadIdx.x) * 2;
    int is64 = g_is64;
    if (e0 + 1 < NEDGES) {
        int d0, d1;
        if (is64) {
            longlong2 v = __ldg(&((const longlong2*)dst)[e0 >> 1]);
            d0 = (int)v.x; d1 = (int)v.y;
        } else {
            int2 v = __ldg(&((const int2*)dst)[e0 >> 1]);
            d0 = v.x; d1 = v.y;
        }
        atomicAdd(&g_deg[d0], 1);
        atomicAdd(&g_deg[d1], 1);
    } else if (e0 < NEDGES) {
        atomicAdd(&g_deg[load_idx(dst, e0, is64)], 1);
    }
}
__global__ void k_scan1() {
    __shared__ int sm[SCAN_CHUNK];
    int b = blockIdx.x, tid = threadIdx.x;
    int idx = b * SCAN_CHUNK + tid;
    int v = (idx < NNODES) ? g_deg[idx] : 0;
    sm[tid] = v;
    __syncthreads();
    for (int s = 1; s < SCAN_CHUNK; s <<= 1) {
        int t = (tid >= s) ? sm[tid - s] : 0;
        __syncthreads();
        sm[tid] += t;
        __syncthreads();
    }
    if (idx < NNODES) g_rowptr[idx] = sm[tid] - v;
    if (tid == SCAN_CHUNK - 1) g_bsum[b] = sm[tid];
}
__global__ void k_scan2() {
    __shared__ int sm[128];
    int tid = threadIdx.x;
    int v = (tid < SCAN_NB) ? g_bsum[tid] : 0;
    sm[tid] = v;
    __syncthreads();
    for (int s = 1; s < 128; s <<= 1) {
        int t = (tid >= s) ? sm[tid - s] : 0;
        __syncthreads();
        sm[tid] += t;
        __syncthreads();
    }
    if (tid < SCAN_NB) g_boff[tid] = sm[tid] - v;
    if (tid == 127) g_rowptr[NNODES] = sm[127];
}
__global__ void k_scan3() {
    int i = blockIdx.x * blockDim.x + threadIdx.x;
    if (i < NNODES) {
        int r = g_rowptr[i] + g_boff[i >> 10];
        g_rowptr[i] = r;
        g_cursor[i] = r;
    }
}
__global__ void k_scatter(const void* __restrict__ src,
                          const void* __restrict__ dst) {
    int e0 = (blockIdx.x * blockDim.x + threadIdx.x) * 2;
    int is64 = g_is64;
    if (e0 + 1 < NEDGES) {
        int s0, s1, d0, d1;
        if (is64) {
            longlong2 vs = __ldg(&((const longlong2*)src)[e0 >> 1]);
            longlong2 vd = __ldg(&((const longlong2*)dst)[e0 >> 1]);
            s0 = (int)vs.x; s1 = (int)vs.y;
            d0 = (int)vd.x; d1 = (int)vd.y;
        } else {
            int2 vs = __ldg(&((const int2*)src)[e0 >> 1]);
            int2 vd = __ldg(&((const int2*)dst)[e0 >> 1]);
            s0 = vs.x; s1 = vs.y;
            d0 = vd.x; d1 = vd.y;
        }
        int p0 = atomicAdd(&g_cursor[d0], 1);
        g_edgesrc[p0] = s0;
        int p1 = atomicAdd(&g_cursor[d1], 1);
        g_edgesrc[p1] = s1;
    } else if (e0 < NEDGES) {
        int d = load_idx(dst, e0, is64);
        int pos = atomicAdd(&g_cursor[d], 1);
        g_edgesrc[pos] = load_idx(src, e0, is64);
    }
}

// ---------------- aggregation: h0 = fp16((1+eps)*x + sum xh[src]) --------------
__global__ __launch_bounds__(256) void k_aggregate(
    const float* __restrict__ x, const float* __restrict__ eps) {
    int warp = threadIdx.x >> 5;             // 0..7
    int t = threadIdx.x & 31;                // 16B chunk within row
    int n = blockIdx.x * 8 + warp;
    if (n >= NNODES) return;
    const uint4* xh4 = (const uint4*)g_xh;   // 32 uint4 per row

    int beg = g_rowptr[n];
    int end = g_rowptr[n + 1];
    float a[8] = {0.f, 0.f, 0.f, 0.f, 0.f, 0.f, 0.f, 0.f};
    int j = beg;
    for (; j + 4 <= end; j += 4) {
        int s0 = g_edgesrc[j];
        int s1 = g_edgesrc[j + 1];
        int s2 = g_edgesrc[j + 2];
        int s3 = g_edgesrc[j + 3];
        uint4 v0 = __ldg(&xh4[(size_t)s0 * 32 + t]);
        uint4 v1 = __ldg(&xh4[(size_t)s1 * 32 + t]);
        uint4 v2 = __ldg(&xh4[(size_t)s2 * 32 + t]);
        uint4 v3 = __ldg(&xh4[(size_t)s3 * 32 + t]);
        acc8(a, v0); acc8(a, v1); acc8(a, v2); acc8(a, v3);
    }
    for (; j < end; j++) {
        uint4 v = __ldg(&xh4[(size_t)g_edgesrc[j] * 32 + t]);
        acc8(a, v);
    }
    float e0 = 1.f + __ldg(&eps[0]);
    const float4* x4 = (const float4*)x;
    float4 s0 = __ldg(&x4[(size_t)n * 64 + t * 2]);
    float4 s1 = __ldg(&x4[(size_t)n * 64 + t * 2 + 1]);
    uint4 o;
    *(__half2*)&o.x = __floats2half2_rn(e0 * s0.x + a[0], e0 * s0.y + a[1]);
    *(__half2*)&o.y = __floats2half2_rn(e0 * s0.z + a[2], e0 * s0.w + a[3]);
    *(__half2*)&o.z = __floats2half2_rn(e0 * s1.x + a[4], e0 * s1.y + a[5]);
    *(__half2*)&o.w = __floats2half2_rn(e0 * s1.z + a[6], e0 * s1.w + a[7]);
    ((uint4*)g_h0)[(size_t)n * 32 + t] = o;
}

// ---------------- fp16 mma.sync m16n8k16 GEMM, cp.async + ldmatrix -------------
// which==0: A=g_h0 [M,256]h, B=g_WT1 -> C=g_h1 [M,512]h, ReLU
// which==1: A=g_h1 [M,512]h, B=g_WT2 -> C=g_h2 [M,256]f, fused BN stats
#define GBM 128
#define GBN 128
#define GBK 32       // halfs per k-tile
#define SPAD 20      // uint32 (half2) per smem row: 16 data + 4 pad = 80B

__global__ __launch_bounds__(256, 2)
void k_gemm_tc(int which, const float* __restrict__ bias, int M, int N, int K) {
    const __half* A  = which ? g_h1 : g_h0;
    const __half* Bw = which ? g_WT2 : g_WT1;
    const int do_relu = (which == 0);

    __shared__ uint32_t sA[2][GBM * SPAD];   // 2 stages x 10KB
    __shared__ uint32_t sB[2][GBM * SPAD];
    __shared__ float s_bns[GBN], s_bnq[GBN];

    int tid = threadIdx.x;
    int wid = tid >> 5;
    int lane = tid & 31;
    int warp_m = wid & 1;        // 2 warps along M (64 rows each)
    int warp_n = wid >> 1;       // 4 warps along N (32 cols each)
    int row0 = blockIdx.y * GBM;
    int col0 = blockIdx.x * GBN;
    int gid = lane >> 2;         // 0..7
    int tig = lane & 3;          // 0..3

    uint32_t saBase = smem_u32(&sA[0][0]);
    uint32_t sbBase = smem_u32(&sB[0][0]);

    // ldmatrix per-lane row offsets (uint32 units)
    // A x4: lanes 0-15 -> rows m0..m15 @k0; lanes 16-31 -> rows @ +8 halfs
    uint32_t arow[4];
#pragma unroll
    for (int mt = 0; mt < 4; mt++)
        arow[mt] = (uint32_t)((warp_m * 64 + mt * 16 + (lane & 15)) * SPAD +
                              ((lane >> 4) << 2));
    // B x2: lanes 0-7 -> n-rows @k0; lanes 8-15 -> @ +8 halfs (16-31 mirror)
    uint32_t brow[4];
#pragma unroll
    for (int nt = 0; nt < 4; nt++)
        brow[nt] = (uint32_t)((warp_n * 32 + nt * 8 + (lane & 7)) * SPAD +
                              (((lane >> 3) & 1) << 2));

    float acc[4][4][4];
#pragma unroll
    for (int i = 0; i < 4; i++)
#pragma unroll
        for (int j = 0; j < 4; j++)
#pragma unroll
            for (int c = 0; c < 4; c++) acc[i][j][c] = 0.f;

    auto issue = [&](int kt, int buf) {
#pragma unroll
        for (int i = 0; i < 2; i++) {
            int lin = i * 256 + tid;
            int row = lin >> 2;
            int f = lin & 3;
            uint32_t off = (uint32_t)(buf * GBM * SPAD + row * SPAD + f * 4) * 4u;
            int gr = row0 + row;
            int sz = (gr < M) ? 16 : 0;
            CP_ASYNC16Z(saBase + off, A + (size_t)gr * K + kt + f * 8, sz);
            CP_ASYNC16(sbBase + off, Bw + (size_t)(col0 + row) * K + kt + f * 8);
        }
        CP_COMMIT();
    };

    const int T = K / GBK;
    issue(0, 0);
    for (int t = 0; t < T; t++) {
        if (t + 1 < T) {
            issue((t + 1) * GBK, (t + 1) & 1);
            CP_WAIT(1);
        } else {
            CP_WAIT(0);
        }
        __syncthreads();
        uint32_t bufo = (uint32_t)(t & 1) * GBM * SPAD;
#pragma unroll
        for (int kh = 0; kh < GBK / 2; kh += 8) {     // half2 units: 0, 8
            uint32_t af[4][4], bf[4][2];
#pragma unroll
            for (int mt = 0; mt < 4; mt++) {
                uint32_t addr = saBase + (bufo + arow[mt] + kh) * 4u;
                asm volatile(
                    "ldmatrix.sync.aligned.m8n8.x4.shared.b16 {%0,%1,%2,%3}, [%4];"
                    : "=r"(af[mt][0]), "=r"(af[mt][1]),
                      "=r"(af[mt][2]), "=r"(af[mt][3]) : "r"(addr));
            }
#pragma unroll
            for (int nt = 0; nt < 4; nt++) {
                uint32_t addr = sbBase + (bufo + brow[nt] + kh) * 4u;
                asm volatile(
                    "ldmatrix.sync.aligned.m8n8.x2.shared.b16 {%0,%1}, [%2];"
                    : "=r"(bf[nt][0]), "=r"(bf[nt][1]) : "r"(addr));
            }
#pragma unroll
            for (int mt = 0; mt < 4; mt++)
#pragma unroll
                for (int nt = 0; nt < 4; nt++) {
                    asm volatile(
                        "mma.sync.aligned.m16n8k16.row.col.f32.f16.f16.f32 "
                        "{%0,%1,%2,%3}, {%4,%5,%6,%7}, {%8,%9}, {%0,%1,%2,%3};"
                        : "+f"(acc[mt][nt][0]), "+f"(acc[mt][nt][1]),
                          "+f"(acc[mt][nt][2]), "+f"(acc[mt][nt][3])
                        : "r"(af[mt][0]), "r"(af[mt][1]), "r"(af[mt][2]), "r"(af[mt][3]),
                          "r"(bf[nt][0]), "r"(bf[nt][1]));
                }
        }
        __syncthreads();
    }

    // epilogue
    if (which == 1) {
        if (tid < GBN) { s_bns[tid] = 0.f; s_bnq[tid] = 0.f; }
        __syncthreads();
    }
    float cs[4][2], cq[4][2];
#pragma unroll
    for (int nt = 0; nt < 4; nt++) {
        cs[nt][0] = cs[nt][1] = cq[nt][0] = cq[nt][1] = 0.f;
        int cb = col0 + warp_n * 32 + nt * 8 + 2 * tig;
        float bv0 = __ldg(&bias[cb]);
        float bv1 = __ldg(&bias[cb + 1]);
#pragma unroll
        for (int mt = 0; mt < 4; mt++) {
            int r = row0 + warp_m * 64 + mt * 16 + gid;
            float v0 = acc[mt][nt][0] + bv0;
            float v1 = acc[mt][nt][1] + bv1;
            float v2 = acc[mt][nt][2] + bv0;
            float v3 = acc[mt][nt][3] + bv1;
            if (do_relu) {
                v0 = fmaxf(v0, 0.f); v1 = fmaxf(v1, 0.f);
                v2 = fmaxf(v2, 0.f); v3 = fmaxf(v3, 0.f);
                if (r < M)
                    *(__half2*)&g_h1[(size_t)r * N + cb] = __floats2half2_rn(v0, v1);
                if (r + 8 < M)
                    *(__half2*)&g_h1[(size_t)(r + 8) * N + cb] = __floats2half2_rn(v2, v3);
            } else {
                if (r < M) {
                    *(float2*)&g_h2[(size_t)r * N + cb] = make_float2(v0, v1);
                    cs[nt][0] += v0; cq[nt][0] += v0 * v0;
                    cs[nt][1] += v1; cq[nt][1] += v1 * v1;
                }
                if (r + 8 < M) {
                    *(float2*)&g_h2[(size_t)(r + 8) * N + cb] = make_float2(v2, v3);
                    cs[nt][0] += v2; cq[nt][0] += v2 * v2;
                    cs[nt][1] += v3; cq[nt][1] += v3 * v3;
                }
            }
        }
    }
    if (which == 1) {
#pragma unroll
        for (int nt = 0; nt < 4; nt++) {
            int cl = warp_n * 32 + nt * 8 + 2 * tig;
            atomicAdd(&s_bns[cl], cs[nt][0]);
            atomicAdd(&s_bns[cl + 1], cs[nt][1]);
            atomicAdd(&s_bnq[cl], cq[nt][0]);
            atomicAdd(&s_bnq[cl + 1], cq[nt][1]);
        }
        __syncthreads();
        if (tid < GBN) {
            atomicAdd(&g_bnsum[col0 + tid], s_bns[tid]);
            atomicAdd(&g_bnsumsq[col0 + tid], s_bnq[tid]);
        }
    }
}

// ---------------- normalize (BN finalize inlined per block) --------------------
__global__ __launch_bounds__(256) void k_norm(
    float* __restrict__ out,
    const float* __restrict__ gamma, const float* __restrict__ beta) {
    __shared__ float ssc[DIM], ssh[DIM];
    int d = threadIdx.x;
    float mean = g_bnsum[d] * (1.0f / (float)NNODES);
    float var = g_bnsumsq[d] * (1.0f / (float)NNODES) - mean * mean;
    float inv = rsqrtf(var + BN_EPS);
    float sc = inv * __ldg(&gamma[d]);
    ssc[d] = sc;
    ssh[d] = __ldg(&beta[d]) - mean * sc;
    __syncthreads();

    const float4* in4 = (const float4*)g_h2;
    float4* out4 = (float4*)out;
    int base = (blockIdx.x * 1024 + threadIdx.x);
#pragma unroll
    for (int it = 0; it < 4; it++) {
        int i = base + it * 256;
        if (i < NNODES * DIM / 4) {
            int dd = (i * 4) & (DIM - 1);
            float4 v = in4[i];
            float4 o;
            o.x = v.x * ssc[dd + 0] + ssh[dd + 0];
            o.y = v.y * ssc[dd + 1] + ssh[dd + 1];
            o.z = v.z * ssc[dd + 2] + ssh[dd + 2];
            o.w = v.w * ssc[dd + 3] + ssh[dd + 3];
            out4[i] = o;
        }
    }
}

// ---------------- launch -------------------------------------------------------
extern "C" void kernel_launch(void* const* d_in, const int* in_sizes, int n_in,
                              void* d_out, int out_size) {
    const float* node_feats = (const float*)d_in[0];
    const void* src         = d_in[1];
    const void* dst         = d_in[2];
    const float* eps        = (const float*)d_in[3];
    const float* W1         = (const float*)d_in[4];
    const float* b1         = (const float*)d_in[5];
    const float* W2         = (const float*)d_in[6];
    const float* b2         = (const float*)d_in[7];
    const float* gamma      = (const float*)d_in[8];
    const float* beta       = (const float*)d_in[9];
    float* out = (float*)d_out;

    // fused prep: fp16 mirror of x, zero/detect, weight transposes
    k_prep<<<PREP_BLOCKS, 256>>>(node_feats, W1, W2, (const int*)dst);

    // CSR build
    k_hist<<<(NEDGES / 2 + 255) / 256, 256>>>(dst);
    k_scan1<<<SCAN_NB, SCAN_CHUNK>>>();
    k_scan2<<<1, 128>>>();
    k_scan3<<<(NNODES + 255) / 256, 256>>>();
    k_scatter<<<(NEDGES / 2 + 255) / 256, 256>>>(src, dst);

    // aggregation -> h0 fp16; 8 nodes per block (1 warp each)
    k_aggregate<<<(NNODES + 7) / 8, 256>>>(node_feats, eps);

    const int MROWS = (NNODES + GBM - 1) / GBM;   // 782
    // GEMM1: h1 = fp16(relu(h0 @ W1 + b1))
    k_gemm_tc<<<dim3(DIM2 / GBN, MROWS), 256>>>(0, b1, NNODES, DIM2, DIM);
    // GEMM2: h2 = h1 @ W2 + b2 (f32) + BN stats
    k_gemm_tc<<<dim3(DIM / GBN, MROWS), 256>>>(1, b2, NNODES, DIM, DIM2);

    // normalize (BN finalize inlined)
    k_norm<<<(NNODES * DIM / 4 + 1023) / 1024, 256>>>(out, gamma, beta);
}

// round 13
// speedup vs baseline: 1.6167x; 1.0157x over previous
#include <cuda_runtime.h>
#include <cuda_fp16.h>
#include <cstdint>

#define NNODES 100000
#define NEDGES 1600000
#define DIM 256
#define DIM2 512
#define BN_EPS 1e-5f

// ---------------- scratch (static device globals; no dynamic alloc) -----------
__device__ int    g_is64;
__device__ int    g_deg[NNODES];
__device__ int    g_rowptr[NNODES + 1];
__device__ int    g_cursor[NNODES];
__device__ int    g_edgesrc[NEDGES];
__device__ __half g_xh[(size_t)NNODES * DIM];      // x, fp16 mirror
__device__ __half g_h0[(size_t)NNODES * DIM];      // h0, fp16
__device__ __half g_h1[(size_t)NNODES * DIM2];     // h1, fp16
__device__ float  g_h2[(size_t)NNODES * DIM];      // h2, f32
__device__ __half g_WT1[(size_t)DIM2 * DIM];       // W1^T [512][256] fp16
__device__ __half g_WT2[(size_t)DIM * DIM2];       // W2^T [256][512] fp16
__device__ float  g_bnsum[DIM];
__device__ float  g_bnsumsq[DIM];

#define SCAN_CHUNK 1024
#define SCAN_NB ((NNODES + SCAN_CHUNK - 1) / SCAN_CHUNK)   // 98
__device__ int g_bsum[SCAN_NB];

// ---------------- helpers ------------------------------------------------------
__device__ __forceinline__ uint32_t smem_u32(const void* p) {
    uint32_t a;
    asm("{ .reg .u64 t; cvta.to.shared.u64 t, %1; cvt.u32.u64 %0, t; }"
        : "=r"(a) : "l"(p));
    return a;
}
#define CP_ASYNC16Z(dst, src, sz) \
    asm volatile("cp.async.cg.shared.global [%0], [%1], 16, %2;" \
                 :: "r"(dst), "l"(src), "r"(sz) : "memory")
#define CP_ASYNC16(dst, src) \
    asm volatile("cp.async.cg.shared.global [%0], [%1], 16;" \
                 :: "r"(dst), "l"(src) : "memory")
#define CP_COMMIT() asm volatile("cp.async.commit_group;" ::: "memory")
#define CP_WAIT(n)  asm volatile("cp.async.wait_group %0;" :: "n"(n) : "memory")

__device__ __forceinline__ int load_idx(const void* p, int e, int is64) {
    return is64 ? (int)((const long long*)p)[e] : ((const int*)p)[e];
}
__device__ __forceinline__ void acc8(float* a, uint4 v) {
    float2 f0 = __half22float2(*(__half2*)&v.x);
    float2 f1 = __half22float2(*(__half2*)&v.y);
    float2 f2 = __half22float2(*(__half2*)&v.z);
    float2 f3 = __half22float2(*(__half2*)&v.w);
    a[0] += f0.x; a[1] += f0.y; a[2] += f1.x; a[3] += f1.y;
    a[4] += f2.x; a[5] += f2.y; a[6] += f3.x; a[7] += f3.y;
}

// ---------------- fused prep: xhalf | zero+detect | transposes -----------------
#define XH_BLOCKS (NNODES * DIM / 8 / 256)               // 12500
#define ZERO_BLOCKS ((NNODES + 255) / 256)               // 391
#define PREP_BLOCKS (XH_BLOCKS + ZERO_BLOCKS + 512)

__global__ __launch_bounds__(256) void k_prep(
    const float* __restrict__ x, const float* __restrict__ W1,
    const float* __restrict__ W2, const int* __restrict__ dst_raw) {
    int b = blockIdx.x;
    int tid = threadIdx.x;
    if (b < XH_BLOCKS) {
        int i = b * 256 + tid;
        const float4* x4 = (const float4*)x;
        float4 v0 = __ldg(&x4[i * 2]);
        float4 v1 = __ldg(&x4[i * 2 + 1]);
        uint4 o;
        *(__half2*)&o.x = __floats2half2_rn(v0.x, v0.y);
        *(__half2*)&o.y = __floats2half2_rn(v0.z, v0.w);
        *(__half2*)&o.z = __floats2half2_rn(v1.x, v1.y);
        *(__half2*)&o.w = __floats2half2_rn(v1.z, v1.w);
        ((uint4*)g_xh)[i] = o;
    } else if (b < XH_BLOCKS + ZERO_BLOCKS) {
        int i = (b - XH_BLOCKS) * 256 + tid;
        if (i < NNODES) g_deg[i] = 0;
        if (i < DIM) { g_bnsum[i] = 0.f; g_bnsumsq[i] = 0.f; }
        if (i == 0) {
            int is64 = 1;
            for (int k = 0; k < 64; k++)
                if (dst_raw[2 * k + 1] != 0) { is64 = 0; break; }
            g_is64 = is64;
        }
    } else {
        __shared__ float t[32][33];
        int w = b - XH_BLOCKS - ZERO_BLOCKS;   // 0..511
        int which = w >> 8;
        int rem = w & 255;
        int bx = (rem & 15) * 32, by = (rem >> 4) * 32;
        const float* W = which ? W2 : W1;
        __half* outp   = which ? g_WT2 : g_WT1;
        int rows = which ? DIM2 : DIM;
        int cols = which ? DIM : DIM2;
        if (bx >= cols || by >= rows) return;
        int tx = tid & 31, ty = tid >> 5;      // 32 x 8
        for (int i = ty; i < 32; i += 8)
            t[i][tx] = W[(size_t)(by + i) * cols + bx + tx];
        __syncthreads();
        for (int i = ty; i < 32; i += 8)
            outp[(size_t)(bx + i) * rows + by + tx] = __float2half_rn(t[tx][i]);
    }
}

// ---------------- CSR build ----------------------------------------------------
__global__ void k_hist(const void* __restrict__ dst) {
    int e0 = (blockIdx.x * blockDim.x + threadIdx.x) * 2;
    int is64 = g_is64;
    if (e0 + 1 < NEDGES) {
        int d0, d1;
        if (is64) {
            longlong2 v = __ldg(&((const longlong2*)dst)[e0 >> 1]);
            d0 = (int)v.x; d1 = (int)v.y;
        } else {
            int2 v = __ldg(&((const int2*)dst)[e0 >> 1]);
            d0 = v.x; d1 = v.y;
        }
        atomicAdd(&g_deg[d0], 1);
        atomicAdd(&g_deg[d1], 1);
    } else if (e0 < NEDGES) {
        atomicAdd(&g_deg[load_idx(dst, e0, is64)], 1);
    }
}
__global__ void k_scan1() {
    __shared__ int sm[SCAN_CHUNK];
    int b = blockIdx.x, tid = threadIdx.x;
    int idx = b * SCAN_CHUNK + tid;
    int v = (idx < NNODES) ? g_deg[idx] : 0;
    sm[tid] = v;
    __syncthreads();
    for (int s = 1; s < SCAN_CHUNK; s <<= 1) {
        int t = (tid >= s) ? sm[tid - s] : 0;
        __syncthreads();
        sm[tid] += t;
        __syncthreads();
    }
    if (idx < NNODES) g_rowptr[idx] = sm[tid] - v;   // block-local exclusive
    if (tid == SCAN_CHUNK - 1) g_bsum[b] = sm[tid];
}
// scan of 98 block partials redone per block (cheap, kills a launch + bubble)
__global__ void k_scan3() {
    __shared__ int sm[128];
    int tid = threadIdx.x;
    int b = blockIdx.x;
    int v = (tid < SCAN_NB) ? g_bsum[tid] : 0;
    if (tid < 128) sm[tid] = v;
    __syncthreads();
    for (int s = 1; s < 128; s <<= 1) {
        int t = (tid >= s && tid < 128) ? sm[tid - s] : 0;
        __syncthreads();
        if (tid < 128) sm[tid] += t;
        __syncthreads();
    }
    // sm[k] = inclusive sum; block-chunk offset for chunk c is sm[c] - bsum[c]
    int i = b * 256 + tid;
    if (i < NNODES) {
        int c = i >> 10;
        int off = sm[c] - g_bsum[c];
        int r = g_rowptr[i] + off;
        g_rowptr[i] = r;
        g_cursor[i] = r;
    }
    if (b == 0 && tid == 127) g_rowptr[NNODES] = sm[SCAN_NB - 1] +
        (SCAN_NB < 128 ? 0 : 0);   // sm[97] inclusive over all chunks
}

__global__ void k_scatter(const void* __restrict__ src,
                          const void* __restrict__ dst) {
    int e0 = (blockIdx.x * blockDim.x + threadIdx.x) * 2;
    int is64 = g_is64;
    if (e0 + 1 < NEDGES) {
        int s0, s1, d0, d1;
        if (is64) {
            longlong2 vs = __ldg(&((const longlong2*)src)[e0 >> 1]);
            longlong2 vd = __ldg(&((const longlong2*)dst)[e0 >> 1]);
            s0 = (int)vs.x; s1 = (int)vs.y;
            d0 = (int)vd.x; d1 = (int)vd.y;
        } else {
            int2 vs = __ldg(&((const int2*)src)[e0 >> 1]);
            int2 vd = __ldg(&((const int2*)dst)[e0 >> 1]);
            s0 = vs.x; s1 = vs.y;
            d0 = vd.x; d1 = vd.y;
        }
        int p0 = atomicAdd(&g_cursor[d0], 1);
        g_edgesrc[p0] = s0;
        int p1 = atomicAdd(&g_cursor[d1], 1);
        g_edgesrc[p1] = s1;
    } else if (e0 < NEDGES) {
        int d = load_idx(dst, e0, is64);
        int pos = atomicAdd(&g_cursor[d], 1);
        g_edgesrc[pos] = load_idx(src, e0, is64);
    }
}

// ---------------- aggregation: h0 = fp16((1+eps)*xh + sum xh[src]) -------------
__global__ __launch_bounds__(256) void k_aggregate(const float* __restrict__ eps) {
    int warp = threadIdx.x >> 5;             // 0..7
    int t = threadIdx.x & 31;                // 16B chunk within row
    int n = blockIdx.x * 8 + warp;
    if (n >= NNODES) return;
    const uint4* xh4 = (const uint4*)g_xh;   // 32 uint4 per row

    int beg = g_rowptr[n];
    int end = g_rowptr[n + 1];
    float a[8] = {0.f, 0.f, 0.f, 0.f, 0.f, 0.f, 0.f, 0.f};
    int j = beg;
    for (; j + 4 <= end; j += 4) {
        int s0 = g_edgesrc[j];
        int s1 = g_edgesrc[j + 1];
        int s2 = g_edgesrc[j + 2];
        int s3 = g_edgesrc[j + 3];
        uint4 v0 = __ldg(&xh4[(size_t)s0 * 32 + t]);
        uint4 v1 = __ldg(&xh4[(size_t)s1 * 32 + t]);
        uint4 v2 = __ldg(&xh4[(size_t)s2 * 32 + t]);
        uint4 v3 = __ldg(&xh4[(size_t)s3 * 32 + t]);
        acc8(a, v0); acc8(a, v1); acc8(a, v2); acc8(a, v3);
    }
    for (; j < end; j++) {
        uint4 v = __ldg(&xh4[(size_t)g_edgesrc[j] * 32 + t]);
        acc8(a, v);
    }
    float e0 = 1.f + __ldg(&eps[0]);
    uint4 sv = __ldg(&xh4[(size_t)n * 32 + t]);
    float s[8] = {0.f, 0.f, 0.f, 0.f, 0.f, 0.f, 0.f, 0.f};
    acc8(s, sv);
    uint4 o;
    *(__half2*)&o.x = __floats2half2_rn(e0 * s[0] + a[0], e0 * s[1] + a[1]);
    *(__half2*)&o.y = __floats2half2_rn(e0 * s[2] + a[2], e0 * s[3] + a[3]);
    *(__half2*)&o.z = __floats2half2_rn(e0 * s[4] + a[4], e0 * s[5] + a[5]);
    *(__half2*)&o.w = __floats2half2_rn(e0 * s[6] + a[6], e0 * s[7] + a[7]);
    ((uint4*)g_h0)[(size_t)n * 32 + t] = o;
}

// ---------------- fp16 mma.sync m16n8k16 GEMM, cp.async + ldmatrix -------------
// which==0: A=g_h0 [M,256]h, B=g_WT1 -> C=g_h1 [M,512]h, ReLU
// which==1: A=g_h1 [M,512]h, B=g_WT2 -> C=g_h2 [M,256]f, fused BN stats
#define GBM 128
#define GBN 128
#define GBK 32       // halfs per k-tile
#define SPAD 20      // uint32 (half2) per smem row: 16 data + 4 pad = 80B

__global__ __launch_bounds__(256, 2)
void k_gemm_tc(int which, const float* __restrict__ bias, int M, int N, int K) {
    const __half* A  = which ? g_h1 : g_h0;
    const __half* Bw = which ? g_WT2 : g_WT1;
    const int do_relu = (which == 0);

    __shared__ uint32_t sA[2][GBM * SPAD];   // 2 stages x 10KB
    __shared__ uint32_t sB[2][GBM * SPAD];
    __shared__ float s_bns[GBN], s_bnq[GBN];

    int tid = threadIdx.x;
    int wid = tid >> 5;
    int lane = tid & 31;
    int warp_m = wid & 1;        // 2 warps along M (64 rows each)
    int warp_n = wid >> 1;       // 4 warps along N (32 cols each)
    int row0 = blockIdx.y * GBM;
    int col0 = blockIdx.x * GBN;
    int gid = lane >> 2;         // 0..7
    int tig = lane & 3;          // 0..3

    uint32_t saBase = smem_u32(&sA[0][0]);
    uint32_t sbBase = smem_u32(&sB[0][0]);

    uint32_t arow[4];
#pragma unroll
    for (int mt = 0; mt < 4; mt++)
        arow[mt] = (uint32_t)((warp_m * 64 + mt * 16 + (lane & 15)) * SPAD +
                              ((lane >> 4) << 2));
    uint32_t brow[4];
#pragma unroll
    for (int nt = 0; nt < 4; nt++)
        brow[nt] = (uint32_t)((warp_n * 32 + nt * 8 + (lane & 7)) * SPAD +
                              (((lane >> 3) & 1) << 2));

    float acc[4][4][4];
#pragma unroll
    for (int i = 0; i < 4; i++)
#pragma unroll
        for (int j = 0; j < 4; j++)
#pragma unroll
            for (int c = 0; c < 4; c++) acc[i][j][c] = 0.f;

    auto issue = [&](int kt, int buf) {
#pragma unroll
        for (int i = 0; i < 2; i++) {
            int lin = i * 256 + tid;
            int row = lin >> 2;
            int f = lin & 3;
            uint32_t off = (uint32_t)(buf * GBM * SPAD + row * SPAD + f * 4) * 4u;
            int gr = row0 + row;
            int sz = (gr < M) ? 16 : 0;
            CP_ASYNC16Z(saBase + off, A + (size_t)gr * K + kt + f * 8, sz);
            CP_ASYNC16(sbBase + off, Bw + (size_t)(col0 + row) * K + kt + f * 8);
        }
        CP_COMMIT();
    };

    const int T = K / GBK;
    issue(0, 0);
    for (int t = 0; t < T; t++) {
        if (t + 1 < T) {
            issue((t + 1) * GBK, (t + 1) & 1);
            CP_WAIT(1);
        } else {
            CP_WAIT(0);
        }
        __syncthreads();
        uint32_t bufo = (uint32_t)(t & 1) * GBM * SPAD;
#pragma unroll
        for (int kh = 0; kh < GBK / 2; kh += 8) {     // half2 units: 0, 8
            uint32_t af[4][4], bf[4][2];
#pragma unroll
            for (int mt = 0; mt < 4; mt++) {
                uint32_t addr = saBase + (bufo + arow[mt] + kh) * 4u;
                asm volatile(
                    "ldmatrix.sync.aligned.m8n8.x4.shared.b16 {%0,%1,%2,%3}, [%4];"
                    : "=r"(af[mt][0]), "=r"(af[mt][1]),
                      "=r"(af[mt][2]), "=r"(af[mt][3]) : "r"(addr));
            }
#pragma unroll
            for (int nt = 0; nt < 4; nt++) {
                uint32_t addr = sbBase + (bufo + brow[nt] + kh) * 4u;
                asm volatile(
                    "ldmatrix.sync.aligned.m8n8.x2.shared.b16 {%0,%1}, [%2];"
                    : "=r"(bf[nt][0]), "=r"(bf[nt][1]) : "r"(addr));
            }
#pragma unroll
            for (int mt = 0; mt < 4; mt++)
#pragma unroll
                for (int nt = 0; nt < 4; nt++) {
                    asm volatile(
                        "mma.sync.aligned.m16n8k16.row.col.f32.f16.f16.f32 "
                        "{%0,%1,%2,%3}, {%4,%5,%6,%7}, {%8,%9}, {%0,%1,%2,%3};"
                        : "+f"(acc[mt][nt][0]), "+f"(acc[mt][nt][1]),
                          "+f"(acc[mt][nt][2]), "+f"(acc[mt][nt][3])
                        : "r"(af[mt][0]), "r"(af[mt][1]), "r"(af[mt][2]), "r"(af[mt][3]),
                          "r"(bf[nt][0]), "r"(bf[nt][1]));
                }
        }
        __syncthreads();
    }

    // epilogue
    if (which == 1) {
        if (tid < GBN) { s_bns[tid] = 0.f; s_bnq[tid] = 0.f; }
        __syncthreads();
    }
    float cs[4][2], cq[4][2];
#pragma unroll
    for (int nt = 0; nt < 4; nt++) {
        cs[nt][0] = cs[nt][1] = cq[nt][0] = cq[nt][1] = 0.f;
        int cb = col0 + warp_n * 32 + nt * 8 + 2 * tig;
        float bv0 = __ldg(&bias[cb]);
        float bv1 = __ldg(&bias[cb + 1]);
#pragma unroll
        for (int mt = 0; mt < 4; mt++) {
            int r = row0 + warp_m * 64 + mt * 16 + gid;
            float v0 = acc[mt][nt][0] + bv0;
            float v1 = acc[mt][nt][1] + bv1;
            float v2 = acc[mt][nt][2] + bv0;
            float v3 = acc[mt][nt][3] + bv1;
            if (do_relu) {
                v0 = fmaxf(v0, 0.f); v1 = fmaxf(v1, 0.f);
                v2 = fmaxf(v2, 0.f); v3 = fmaxf(v3, 0.f);
                if (r < M)
                    *(__half2*)&g_h1[(size_t)r * N + cb] = __floats2half2_rn(v0, v1);
                if (r + 8 < M)
                    *(__half2*)&g_h1[(size_t)(r + 8) * N + cb] = __floats2half2_rn(v2, v3);
            } else {
                if (r < M) {
                    *(float2*)&g_h2[(size_t)r * N + cb] = make_float2(v0, v1);
                    cs[nt][0] += v0; cq[nt][0] += v0 * v0;
                    cs[nt][1] += v1; cq[nt][1] += v1 * v1;
                }
                if (r + 8 < M) {
                    *(float2*)&g_h2[(size_t)(r + 8) * N + cb] = make_float2(v2, v3);
                    cs[nt][0] += v2; cq[nt][0] += v2 * v2;
                    cs[nt][1] += v3; cq[nt][1] += v3 * v3;
                }
            }
        }
    }
    if (which == 1) {
#pragma unroll
        for (int nt = 0; nt < 4; nt++) {
            int cl = warp_n * 32 + nt * 8 + 2 * tig;
            atomicAdd(&s_bns[cl], cs[nt][0]);
            atomicAdd(&s_bns[cl + 1], cs[nt][1]);
            atomicAdd(&s_bnq[cl], cq[nt][0]);
            atomicAdd(&s_bnq[cl + 1], cq[nt][1]);
        }
        __syncthreads();
        if (tid < GBN) {
            atomicAdd(&g_bnsum[col0 + tid], s_bns[tid]);
            atomicAdd(&g_bnsumsq[col0 + tid], s_bnq[tid]);
        }
    }
}

// ---------------- normalize (BN finalize inlined per block) --------------------
// 256 threads/block, 8 float4 per thread
__global__ __launch_bounds__(256) void k_norm(
    float* __restrict__ out,
    const float* __restrict__ gamma, const float* __restrict__ beta) {
    __shared__ float ssc[DIM], ssh[DIM];
    int d = threadIdx.x;
    float mean = g_bnsum[d] * (1.0f / (float)NNODES);
    float var = g_bnsumsq[d] * (1.0f / (float)NNODES) - mean * mean;
    float inv = rsqrtf(var + BN_EPS);
    float sc = inv * __ldg(&gamma[d]);
    ssc[d] = sc;
    ssh[d] = __ldg(&beta[d]) - mean * sc;
    __syncthreads();

    const float4* in4 = (const float4*)g_h2;
    float4* out4 = (float4*)out;
    int base = (blockIdx.x * 2048 + threadIdx.x);
#pragma unroll
    for (int it = 0; it < 8; it++) {
        int i = base + it * 256;
        if (i < NNODES * DIM / 4) {
            int dd = (i * 4) & (DIM - 1);
            float4 v = __ldg(&in4[i]);
            float4 o;
            o.x = v.x * ssc[dd + 0] + ssh[dd + 0];
            o.y = v.y * ssc[dd + 1] + ssh[dd + 1];
            o.z = v.z * ssc[dd + 2] + ssh[dd + 2];
            o.w = v.w * ssc[dd + 3] + ssh[dd + 3];
            out4[i] = o;
        }
    }
}

// ---------------- launch -------------------------------------------------------
extern "C" void kernel_launch(void* const* d_in, const int* in_sizes, int n_in,
                              void* d_out, int out_size) {
    const float* node_feats = (const float*)d_in[0];
    const void* src         = d_in[1];
    const void* dst         = d_in[2];
    const float* eps        = (const float*)d_in[3];
    const float* W1         = (const float*)d_in[4];
    const float* b1         = (const float*)d_in[5];
    const float* W2         = (const float*)d_in[6];
    const float* b2         = (const float*)d_in[7];
    const float* gamma      = (const float*)d_in[8];
    const float* beta       = (const float*)d_in[9];
    float* out = (float*)d_out;

    // fused prep: fp16 mirror of x, zero/detect, weight transposes
    k_prep<<<PREP_BLOCKS, 256>>>(node_feats, W1, W2, (const int*)dst);

    // CSR build (scan2 folded into scan3)
    k_hist<<<(NEDGES / 2 + 255) / 256, 256>>>(dst);
    k_scan1<<<SCAN_NB, SCAN_CHUNK>>>();
    k_scan3<<<(NNODES + 255) / 256, 256>>>();
    k_scatter<<<(NEDGES / 2 + 255) / 256, 256>>>(src, dst);

    // aggregation -> h0 fp16; 8 nodes per block (1 warp each)
    k_aggregate<<<(NNODES + 7) / 8, 256>>>(eps);

    const int MROWS = (NNODES + GBM - 1) / GBM;   // 782
    // GEMM1: h1 = fp16(relu(h0 @ W1 + b1))
    k_gemm_tc<<<dim3(DIM2 / GBN, MROWS), 256>>>(0, b1, NNODES, DIM2, DIM);
    // GEMM2: h2 = h1 @ W2 + b2 (f32) + BN stats
    k_gemm_tc<<<dim3(DIM / GBN, MROWS), 256>>>(1, b2, NNODES, DIM, DIM2);

    // normalize (BN finalize inlined)
    k_norm<<<(NNODES * DIM / 4 + 2047) / 2048, 256>>>(out, gamma, beta);
}

// round 14
// speedup vs baseline: 1.6363x; 1.0121x over previous
#include <cuda_runtime.h>
#include <cuda_fp16.h>
#include <cstdint>

#define NNODES 100000
#define NEDGES 1600000
#define DIM 256
#define DIM2 512
#define BN_EPS 1e-5f

// ---------------- scratch (static device globals; no dynamic alloc) -----------
__device__ int    g_is64;
__device__ int    g_deg[NNODES];
__device__ int    g_rowptr[NNODES + 1];
__device__ int    g_cursor[NNODES];
__device__ int    g_edgesrc[NEDGES];
__device__ __half g_xh[(size_t)NNODES * DIM];      // x, fp16 mirror
__device__ __half g_h0[(size_t)NNODES * DIM];      // h0, fp16
__device__ __half g_h1[(size_t)NNODES * DIM2];     // h1, fp16
__device__ float  g_h2[(size_t)NNODES * DIM];      // h2, f32
__device__ __half g_WT1[(size_t)DIM2 * DIM];       // W1^T [512][256] fp16
__device__ __half g_WT2[(size_t)DIM * DIM2];       // W2^T [256][512] fp16
__device__ float  g_bnsum[DIM];
__device__ float  g_bnsumsq[DIM];

#define SCAN_CHUNK 1024
#define SCAN_NB ((NNODES + SCAN_CHUNK - 1) / SCAN_CHUNK)   // 98
__device__ int g_bsum[SCAN_NB];

// ---------------- helpers ------------------------------------------------------
__device__ __forceinline__ uint32_t smem_u32(const void* p) {
    uint32_t a;
    asm("{ .reg .u64 t; cvta.to.shared.u64 t, %1; cvt.u32.u64 %0, t; }"
        : "=r"(a) : "l"(p));
    return a;
}
#define CP_ASYNC16Z(dst, src, sz) \
    asm volatile("cp.async.cg.shared.global [%0], [%1], 16, %2;" \
                 :: "r"(dst), "l"(src), "r"(sz) : "memory")
#define CP_ASYNC16(dst, src) \
    asm volatile("cp.async.cg.shared.global [%0], [%1], 16;" \
                 :: "r"(dst), "l"(src) : "memory")
#define CP_COMMIT() asm volatile("cp.async.commit_group;" ::: "memory")
#define CP_WAIT(n)  asm volatile("cp.async.wait_group %0;" :: "n"(n) : "memory")

__device__ __forceinline__ int load_idx(const void* p, int e, int is64) {
    return is64 ? (int)((const long long*)p)[e] : ((const int*)p)[e];
}
__device__ __forceinline__ void acc8(float* a, uint4 v) {
    float2 f0 = __half22float2(*(__half2*)&v.x);
    float2 f1 = __half22float2(*(__half2*)&v.y);
    float2 f2 = __half22float2(*(__half2*)&v.z);
    float2 f3 = __half22float2(*(__half2*)&v.w);
    a[0] += f0.x; a[1] += f0.y; a[2] += f1.x; a[3] += f1.y;
    a[4] += f2.x; a[5] += f2.y; a[6] += f3.x; a[7] += f3.y;
}

// ---------------- zero + index-dtype detect (prereq of everything) -------------
__global__ void k_zero(const int* __restrict__ dst_raw) {
    int i = blockIdx.x * blockDim.x + threadIdx.x;
    if (i < NNODES) g_deg[i] = 0;
    if (i < DIM) { g_bnsum[i] = 0.f; g_bnsumsq[i] = 0.f; }
    if (i == 0) {
        int is64 = 1;
        for (int k = 0; k < 64; k++)
            if (dst_raw[2 * k + 1] != 0) { is64 = 0; break; }
        g_is64 = is64;
    }
}

// ---------------- fused hist | xhalf | transposes (all independent) ------------
#define HIST_BLOCKS ((NEDGES / 2 + 255) / 256)           // 3125
#define XH_BLOCKS (NNODES * DIM / 8 / 256)               // 12500
#define HP_BLOCKS (HIST_BLOCKS + XH_BLOCKS + 512)

__global__ __launch_bounds__(256) void k_histprep(
    const void* __restrict__ dst, const float* __restrict__ x,
    const float* __restrict__ W1, const float* __restrict__ W2) {
    int b = blockIdx.x;
    int tid = threadIdx.x;
    if (b < HIST_BLOCKS) {
        // degree histogram, 2 edges/thread
        int e0 = (b * 256 + tid) * 2;
        int is64 = g_is64;
        if (e0 + 1 < NEDGES) {
            int d0, d1;
            if (is64) {
                longlong2 v = __ldg(&((const longlong2*)dst)[e0 >> 1]);
                d0 = (int)v.x; d1 = (int)v.y;
            } else {
                int2 v = __ldg(&((const int2*)dst)[e0 >> 1]);
                d0 = v.x; d1 = v.y;
            }
            atomicAdd(&g_deg[d0], 1);
            atomicAdd(&g_deg[d1], 1);
        } else if (e0 < NEDGES) {
            atomicAdd(&g_deg[load_idx(dst, e0, is64)], 1);
        }
    } else if (b < HIST_BLOCKS + XH_BLOCKS) {
        // x -> fp16 mirror
        int i = (b - HIST_BLOCKS) * 256 + tid;
        const float4* x4 = (const float4*)x;
        float4 v0 = __ldg(&x4[i * 2]);
        float4 v1 = __ldg(&x4[i * 2 + 1]);
        uint4 o;
        *(__half2*)&o.x = __floats2half2_rn(v0.x, v0.y);
        *(__half2*)&o.y = __floats2half2_rn(v0.z, v0.w);
        *(__half2*)&o.z = __floats2half2_rn(v1.x, v1.y);
        *(__half2*)&o.w = __floats2half2_rn(v1.z, v1.w);
        ((uint4*)g_xh)[i] = o;
    } else {
        // weight transposes, fp16 outputs
        __shared__ float t[32][33];
        int w = b - HIST_BLOCKS - XH_BLOCKS;   // 0..511
        int which = w >> 8;
        int rem = w & 255;
        int bx = (rem & 15) * 32, by = (rem >> 4) * 32;
        const float* W = which ? W2 : W1;
        __half* outp   = which ? g_WT2 : g_WT1;
        int rows = which ? DIM2 : DIM;
        int cols = which ? DIM : DIM2;
        if (bx >= cols || by >= rows) return;
        int tx = tid & 31, ty = tid >> 5;      // 32 x 8
        for (int i = ty; i < 32; i += 8)
            t[i][tx] = W[(size_t)(by + i) * cols + bx + tx];
        __syncthreads();
        for (int i = ty; i < 32; i += 8)
            outp[(size_t)(bx + i) * rows + by + tx] = __float2half_rn(t[tx][i]);
    }
}

// ---------------- CSR scan -----------------------------------------------------
__global__ void k_scan1() {
    __shared__ int sm[SCAN_CHUNK];
    int b = blockIdx.x, tid = threadIdx.x;
    int idx = b * SCAN_CHUNK + tid;
    int v = (idx < NNODES) ? g_deg[idx] : 0;
    sm[tid] = v;
    __syncthreads();
    for (int s = 1; s < SCAN_CHUNK; s <<= 1) {
        int t = (tid >= s) ? sm[tid - s] : 0;
        __syncthreads();
        sm[tid] += t;
        __syncthreads();
    }
    if (idx < NNODES) g_rowptr[idx] = sm[tid] - v;   // block-local exclusive
    if (tid == SCAN_CHUNK - 1) g_bsum[b] = sm[tid];
}
// per-block rescan of 98 partials + apply offsets (kills a launch + bubble)
__global__ void k_scan3() {
    __shared__ int sm[128];
    int tid = threadIdx.x;
    int b = blockIdx.x;
    int v = (tid < SCAN_NB) ? g_bsum[tid] : 0;
    if (tid < 128) sm[tid] = v;
    __syncthreads();
    for (int s = 1; s < 128; s <<= 1) {
        int t = (tid >= s && tid < 128) ? sm[tid - s] : 0;
        __syncthreads();
        if (tid < 128) sm[tid] += t;
        __syncthreads();
    }
    int i = b * 256 + tid;
    if (i < NNODES) {
        int c = i >> 10;
        int off = sm[c] - g_bsum[c];
        int r = g_rowptr[i] + off;
        g_rowptr[i] = r;
        g_cursor[i] = r;
    }
    if (b == 0 && tid == 127) g_rowptr[NNODES] = sm[SCAN_NB - 1];
}

__global__ void k_scatter(const void* __restrict__ src,
                          const void* __restrict__ dst) {
    int e0 = (blockIdx.x * blockDim.x + threadIdx.x) * 2;
    int is64 = g_is64;
    if (e0 + 1 < NEDGES) {
        int s0, s1, d0, d1;
        if (is64) {
            longlong2 vs = __ldg(&((const longlong2*)src)[e0 >> 1]);
            longlong2 vd = __ldg(&((const longlong2*)dst)[e0 >> 1]);
            s0 = (int)vs.x; s1 = (int)vs.y;
            d0 = (int)vd.x; d1 = (int)vd.y;
        } else {
            int2 vs = __ldg(&((const int2*)src)[e0 >> 1]);
            int2 vd = __ldg(&((const int2*)dst)[e0 >> 1]);
            s0 = vs.x; s1 = vs.y;
            d0 = vd.x; d1 = vd.y;
        }
        int p0 = atomicAdd(&g_cursor[d0], 1);
        g_edgesrc[p0] = s0;
        int p1 = atomicAdd(&g_cursor[d1], 1);
        g_edgesrc[p1] = s1;
    } else if (e0 < NEDGES) {
        int d = load_idx(dst, e0, is64);
        int pos = atomicAdd(&g_cursor[d], 1);
        g_edgesrc[pos] = load_idx(src, e0, is64);
    }
}

// ---------------- aggregation: h0 = fp16((1+eps)*xh + sum xh[src]) -------------
__global__ __launch_bounds__(256) void k_aggregate(const float* __restrict__ eps) {
    int warp = threadIdx.x >> 5;             // 0..7
    int t = threadIdx.x & 31;                // 16B chunk within row
    int n = blockIdx.x * 8 + warp;
    if (n >= NNODES) return;
    const uint4* xh4 = (const uint4*)g_xh;   // 32 uint4 per row

    int beg = g_rowptr[n];
    int end = g_rowptr[n + 1];
    float a[8] = {0.f, 0.f, 0.f, 0.f, 0.f, 0.f, 0.f, 0.f};
    int j = beg;
    for (; j + 4 <= end; j += 4) {
        int s0 = g_edgesrc[j];
        int s1 = g_edgesrc[j + 1];
        int s2 = g_edgesrc[j + 2];
        int s3 = g_edgesrc[j + 3];
        uint4 v0 = __ldg(&xh4[(size_t)s0 * 32 + t]);
        uint4 v1 = __ldg(&xh4[(size_t)s1 * 32 + t]);
        uint4 v2 = __ldg(&xh4[(size_t)s2 * 32 + t]);
        uint4 v3 = __ldg(&xh4[(size_t)s3 * 32 + t]);
        acc8(a, v0); acc8(a, v1); acc8(a, v2); acc8(a, v3);
    }
    for (; j < end; j++) {
        uint4 v = __ldg(&xh4[(size_t)g_edgesrc[j] * 32 + t]);
        acc8(a, v);
    }
    float e0 = 1.f + __ldg(&eps[0]);
    uint4 sv = __ldg(&xh4[(size_t)n * 32 + t]);
    float s[8] = {0.f, 0.f, 0.f, 0.f, 0.f, 0.f, 0.f, 0.f};
    acc8(s, sv);
    uint4 o;
    *(__half2*)&o.x = __floats2half2_rn(e0 * s[0] + a[0], e0 * s[1] + a[1]);
    *(__half2*)&o.y = __floats2half2_rn(e0 * s[2] + a[2], e0 * s[3] + a[3]);
    *(__half2*)&o.z = __floats2half2_rn(e0 * s[4] + a[4], e0 * s[5] + a[5]);
    *(__half2*)&o.w = __floats2half2_rn(e0 * s[6] + a[6], e0 * s[7] + a[7]);
    ((uint4*)g_h0)[(size_t)n * 32 + t] = o;
}

// ---------------- fp16 mma.sync m16n8k16 GEMM, cp.async + ldmatrix -------------
// which==0: A=g_h0 [M,256]h, B=g_WT1 -> C=g_h1 [M,512]h, ReLU
// which==1: A=g_h1 [M,512]h, B=g_WT2 -> C=g_h2 [M,256]f, fused BN stats
#define GBM 128
#define GBN 128
#define GBK 32       // halfs per k-tile
#define SPAD 20      // uint32 (half2) per smem row: 16 data + 4 pad = 80B

__global__ __launch_bounds__(256, 2)
void k_gemm_tc(int which, const float* __restrict__ bias, int M, int N, int K) {
    const __half* A  = which ? g_h1 : g_h0;
    const __half* Bw = which ? g_WT2 : g_WT1;
    const int do_relu = (which == 0);

    __shared__ uint32_t sA[2][GBM * SPAD];   // 2 stages x 10KB
    __shared__ uint32_t sB[2][GBM * SPAD];
    __shared__ float s_bns[GBN], s_bnq[GBN];

    int tid = threadIdx.x;
    int wid = tid >> 5;
    int lane = tid & 31;
    int warp_m = wid & 1;        // 2 warps along M (64 rows each)
    int warp_n = wid >> 1;       // 4 warps along N (32 cols each)
    int row0 = blockIdx.y * GBM;
    int col0 = blockIdx.x * GBN;
    int gid = lane >> 2;         // 0..7
    int tig = lane & 3;          // 0..3

    uint32_t saBase = smem_u32(&sA[0][0]);
    uint32_t sbBase = smem_u32(&sB[0][0]);

    uint32_t arow[4];
#pragma unroll
    for (int mt = 0; mt < 4; mt++)
        arow[mt] = (uint32_t)((warp_m * 64 + mt * 16 + (lane & 15)) * SPAD +
                              ((lane >> 4) << 2));
    uint32_t brow[4];
#pragma unroll
    for (int nt = 0; nt < 4; nt++)
        brow[nt] = (uint32_t)((warp_n * 32 + nt * 8 + (lane & 7)) * SPAD +
                              (((lane >> 3) & 1) << 2));

    float acc[4][4][4];
#pragma unroll
    for (int i = 0; i < 4; i++)
#pragma unroll
        for (int j = 0; j < 4; j++)
#pragma unroll
            for (int c = 0; c < 4; c++) acc[i][j][c] = 0.f;

    auto issue = [&](int kt, int buf) {
#pragma unroll
        for (int i = 0; i < 2; i++) {
            int lin = i * 256 + tid;
            int row = lin >> 2;
            int f = lin & 3;
            uint32_t off = (uint32_t)(buf * GBM * SPAD + row * SPAD + f * 4) * 4u;
            int gr = row0 + row;
            int sz = (gr < M) ? 16 : 0;
            CP_ASYNC16Z(saBase + off, A + (size_t)gr * K + kt + f * 8, sz);
            CP_ASYNC16(sbBase + off, Bw + (size_t)(col0 + row) * K + kt + f * 8);
        }
        CP_COMMIT();
    };

    const int T = K / GBK;
    issue(0, 0);
    for (int t = 0; t < T; t++) {
        if (t + 1 < T) {
            issue((t + 1) * GBK, (t + 1) & 1);
            CP_WAIT(1);
        } else {
            CP_WAIT(0);
        }
        __syncthreads();
        uint32_t bufo = (uint32_t)(t & 1) * GBM * SPAD;
#pragma unroll
        for (int kh = 0; kh < GBK / 2; kh += 8) {     // half2 units: 0, 8
            uint32_t af[4][4], bf[4][2];
#pragma unroll
            for (int mt = 0; mt < 4; mt++) {
                uint32_t addr = saBase + (bufo + arow[mt] + kh) * 4u;
                asm volatile(
                    "ldmatrix.sync.aligned.m8n8.x4.shared.b16 {%0,%1,%2,%3}, [%4];"
                    : "=r"(af[mt][0]), "=r"(af[mt][1]),
                      "=r"(af[mt][2]), "=r"(af[mt][3]) : "r"(addr));
            }
#pragma unroll
            for (int nt = 0; nt < 4; nt++) {
                uint32_t addr = sbBase + (bufo + brow[nt] + kh) * 4u;
                asm volatile(
                    "ldmatrix.sync.aligned.m8n8.x2.shared.b16 {%0,%1}, [%2];"
                    : "=r"(bf[nt][0]), "=r"(bf[nt][1]) : "r"(addr));
            }
#pragma unroll
            for (int mt = 0; mt < 4; mt++)
#pragma unroll
                for (int nt = 0; nt < 4; nt++) {
                    asm volatile(
                        "mma.sync.aligned.m16n8k16.row.col.f32.f16.f16.f32 "
                        "{%0,%1,%2,%3}, {%4,%5,%6,%7}, {%8,%9}, {%0,%1,%2,%3};"
                        : "+f"(acc[mt][nt][0]), "+f"(acc[mt][nt][1]),
                          "+f"(acc[mt][nt][2]), "+f"(acc[mt][nt][3])
                        : "r"(af[mt][0]), "r"(af[mt][1]), "r"(af[mt][2]), "r"(af[mt][3]),
                          "r"(bf[nt][0]), "r"(bf[nt][1]));
                }
        }
        __syncthreads();
    }

    // epilogue
    if (which == 1) {
        if (tid < GBN) { s_bns[tid] = 0.f; s_bnq[tid] = 0.f; }
        __syncthreads();
    }
    float cs[4][2], cq[4][2];
#pragma unroll
    for (int nt = 0; nt < 4; nt++) {
        cs[nt][0] = cs[nt][1] = cq[nt][0] = cq[nt][1] = 0.f;
        int cb = col0 + warp_n * 32 + nt * 8 + 2 * tig;
        float bv0 = __ldg(&bias[cb]);
        float bv1 = __ldg(&bias[cb + 1]);
#pragma unroll
        for (int mt = 0; mt < 4; mt++) {
            int r = row0 + warp_m * 64 + mt * 16 + gid;
            float v0 = acc[mt][nt][0] + bv0;
            float v1 = acc[mt][nt][1] + bv1;
            float v2 = acc[mt][nt][2] + bv0;
            float v3 = acc[mt][nt][3] + bv1;
            if (do_relu) {
                v0 = fmaxf(v0, 0.f); v1 = fmaxf(v1, 0.f);
                v2 = fmaxf(v2, 0.f); v3 = fmaxf(v3, 0.f);
                if (r < M)
                    *(__half2*)&g_h1[(size_t)r * N + cb] = __floats2half2_rn(v0, v1);
                if (r + 8 < M)
                    *(__half2*)&g_h1[(size_t)(r + 8) * N + cb] = __floats2half2_rn(v2, v3);
            } else {
                if (r < M) {
                    *(float2*)&g_h2[(size_t)r * N + cb] = make_float2(v0, v1);
                    cs[nt][0] += v0; cq[nt][0] += v0 * v0;
                    cs[nt][1] += v1; cq[nt][1] += v1 * v1;
                }
                if (r + 8 < M) {
                    *(float2*)&g_h2[(size_t)(r + 8) * N + cb] = make_float2(v2, v3);
                    cs[nt][0] += v2; cq[nt][0] += v2 * v2;
                    cs[nt][1] += v3; cq[nt][1] += v3 * v3;
                }
            }
        }
    }
    if (which == 1) {
#pragma unroll
        for (int nt = 0; nt < 4; nt++) {
            int cl = warp_n * 32 + nt * 8 + 2 * tig;
            atomicAdd(&s_bns[cl], cs[nt][0]);
            atomicAdd(&s_bns[cl + 1], cs[nt][1]);
            atomicAdd(&s_bnq[cl], cq[nt][0]);
            atomicAdd(&s_bnq[cl + 1], cq[nt][1]);
        }
        __syncthreads();
        if (tid < GBN) {
            atomicAdd(&g_bnsum[col0 + tid], s_bns[tid]);
            atomicAdd(&g_bnsumsq[col0 + tid], s_bnq[tid]);
        }
    }
}

// ---------------- normalize (BN finalize inlined per block) --------------------
__global__ __launch_bounds__(256) void k_norm(
    float* __restrict__ out,
    const float* __restrict__ gamma, const float* __restrict__ beta) {
    __shared__ float ssc[DIM], ssh[DIM];
    int d = threadIdx.x;
    float mean = g_bnsum[d] * (1.0f / (float)NNODES);
    float var = g_bnsumsq[d] * (1.0f / (float)NNODES) - mean * mean;
    float inv = rsqrtf(var + BN_EPS);
    float sc = inv * __ldg(&gamma[d]);
    ssc[d] = sc;
    ssh[d] = __ldg(&beta[d]) - mean * sc;
    __syncthreads();

    const float4* in4 = (const float4*)g_h2;
    float4* out4 = (float4*)out;
    int base = (blockIdx.x * 2048 + threadIdx.x);
#pragma unroll
    for (int it = 0; it < 8; it++) {
        int i = base + it * 256;
        if (i < NNODES * DIM / 4) {
            int dd = (i * 4) & (DIM - 1);
            float4 v = __ldg(&in4[i]);
            float4 o;
            o.x = v.x * ssc[dd + 0] + ssh[dd + 0];
            o.y = v.y * ssc[dd + 1] + ssh[dd + 1];
            o.z = v.z * ssc[dd + 2] + ssh[dd + 2];
            o.w = v.w * ssc[dd + 3] + ssh[dd + 3];
            out4[i] = o;
        }
    }
}

// ---------------- launch -------------------------------------------------------
extern "C" void kernel_launch(void* const* d_in, const int* in_sizes, int n_in,
                              void* d_out, int out_size) {
    const float* node_feats = (const float*)d_in[0];
    const void* src         = d_in[1];
    const void* dst         = d_in[2];
    const float* eps        = (const float*)d_in[3];
    const float* W1         = (const float*)d_in[4];
    const float* b1         = (const float*)d_in[5];
    const float* W2         = (const float*)d_in[6];
    const float* b2         = (const float*)d_in[7];
    const float* gamma      = (const float*)d_in[8];
    const float* beta       = (const float*)d_in[9];
    float* out = (float*)d_out;

    // prereqs: zero deg/bn + index dtype detect
    k_zero<<<(NNODES + 255) / 256, 256>>>((const int*)dst);

    // fused: degree histogram | x->fp16 mirror | weight transposes (co-scheduled)
    k_histprep<<<HP_BLOCKS, 256>>>(dst, node_feats, W1, W2);

    // CSR scan + scatter
    k_scan1<<<SCAN_NB, SCAN_CHUNK>>>();
    k_scan3<<<(NNODES + 255) / 256, 256>>>();
    k_scatter<<<(NEDGES / 2 + 255) / 256, 256>>>(src, dst);

    // aggregation -> h0 fp16; 8 nodes per block (1 warp each)
    k_aggregate<<<(NNODES + 7) / 8, 256>>>(eps);

    const int MROWS = (NNODES + GBM - 1) / GBM;   // 782
    // GEMM1: h1 = fp16(relu(h0 @ W1 + b1))
    k_gemm_tc<<<dim3(DIM2 / GBN, MROWS), 256>>>(0, b1, NNODES, DIM2, DIM);
    // GEMM2: h2 = h1 @ W2 + b2 (f32) + BN stats
    k_gemm_tc<<<dim3(DIM / GBN, MROWS), 256>>>(1, b2, NNODES, DIM, DIM2);

    // normalize (BN finalize inlined)
    k_norm<<<(NNODES * DIM / 4 + 2047) / 2048, 256>>>(out, gamma, beta);
}